// round 1
// baseline (speedup 1.0000x reference)
#include <cuda_runtime.h>
#include <math.h>

// ---------------------------------------------------------------------------
// Windowed 3D attention transformer block (Swin-style), fp32 baseline.
// B=2, D=H=W=32, C=512, window 4^3 (N=64 tokens), 8 heads x 64, MLP 4x.
// Rows: 65536 tokens total. Window permutation handled purely via index map.
// ---------------------------------------------------------------------------

#define NROWS   65536
#define CDIM    512
#define QKVDIM  1536
#define HIDDIM  2048

// Scratch (allocation-free: __device__ globals)
__device__ float g_h   [ (size_t)NROWS * CDIM  ];   // LN1 output (windowed order)
__device__ float g_qkv [ (size_t)NROWS * QKVDIM];   // qkv (windowed order)
__device__ float g_attn[ (size_t)NROWS * CDIM  ];   // attention out (windowed order)
__device__ float g_xo  [ (size_t)NROWS * CDIM  ];   // x + proj (spatial order)
__device__ float g_h2  [ (size_t)NROWS * CDIM  ];   // LN2 output (spatial order)
__device__ float g_hid [ (size_t)NROWS * HIDDIM];   // FFN hidden

// Map windowed row index -> flat spatial row index (includes shift of 2).
// r = win*64 + t ; win = ((b*8+wd)*8+wh)*8+ww ; t = td*16+th*4+tw
// spatial = (b, (wd*4+td+2)&31, (wh*4+th+2)&31, (ww*4+tw+2)&31)
__device__ __forceinline__ int mapFlat(int r) {
    int win = r >> 6, t = r & 63;
    int b  = win >> 9;
    int wd = (win >> 6) & 7, wh = (win >> 3) & 7, ww = win & 7;
    int td = t >> 4, th = (t >> 2) & 3, tw = t & 3;
    int d0 = (wd * 4 + td + 2) & 31;
    int h0 = (wh * 4 + th + 2) & 31;
    int w0 = (ww * 4 + tw + 2) & 31;
    return ((b * 32 + d0) * 32 + h0) * 32 + w0;
}

// ---------------------------------------------------------------------------
// LayerNorm: one warp per row of 512. MAPPED=true gathers input row through
// mapFlat (fused cyclic shift + window partition).
// ---------------------------------------------------------------------------
template <bool MAPPED>
__global__ void __launch_bounds__(256) ln_kernel(
    const float* __restrict__ in, const float* __restrict__ gam,
    const float* __restrict__ bet, float* __restrict__ out)
{
    int warp = threadIdx.x >> 5, lane = threadIdx.x & 31;
    int r = blockIdx.x * 8 + warp;
    int src = MAPPED ? mapFlat(r) : r;

    const float4* ip = (const float4*)(in + (size_t)src * CDIM);
    float4 vals[4];
    float s = 0.f, sq = 0.f;
#pragma unroll
    for (int w = 0; w < 4; w++) {
        float4 v = ip[w * 32 + lane];
        vals[w] = v;
        s  += v.x + v.y + v.z + v.w;
        sq += v.x * v.x + v.y * v.y + v.z * v.z + v.w * v.w;
    }
#pragma unroll
    for (int o = 16; o > 0; o >>= 1) {
        s  += __shfl_xor_sync(0xffffffffu, s,  o);
        sq += __shfl_xor_sync(0xffffffffu, sq, o);
    }
    float m  = s * (1.0f / CDIM);
    float var = sq * (1.0f / CDIM) - m * m;
    float rs = rsqrtf(var + 1e-5f);

    float4* op = (float4*)(out + (size_t)r * CDIM);
    const float4* gp = (const float4*)gam;
    const float4* bp = (const float4*)bet;
#pragma unroll
    for (int w = 0; w < 4; w++) {
        int c4 = w * 32 + lane;
        float4 g = gp[c4], b = bp[c4], x = vals[w], o4;
        o4.x = (x.x - m) * rs * g.x + b.x;
        o4.y = (x.y - m) * rs * g.y + b.y;
        o4.z = (x.z - m) * rs * g.z + b.z;
        o4.w = (x.w - m) * rs * g.w + b.w;
        op[c4] = o4;
    }
}

// ---------------------------------------------------------------------------
// SGEMM: C[M,N] = A[M,K] @ B[K,N] (+ epilogue). 128x128 tile, BK=16,
// 256 threads, 8x8 per-thread micro-tile.
// EPI 0: += bias
// EPI 1: gelu(acc + bias)                         (exact GELU)
// EPI 2: out[mapFlat(row)*512+col] = resid[same] + acc + bias  (proj+residual+unshift)
// EPI 3: out[row*N+col] = resid[row*N+col] + acc + bias        (ffn2+residual)
// ---------------------------------------------------------------------------
template <int EPI>
__global__ void __launch_bounds__(256) gemm_kernel(
    const float* __restrict__ A, const float* __restrict__ B,
    const float* __restrict__ bias, const float* __restrict__ resid,
    float* __restrict__ C, int M, int N, int K)
{
    __shared__ float As[16][132];
    __shared__ float Bs[16][128];

    int tid = threadIdx.x;
    int m0 = blockIdx.y * 128, n0 = blockIdx.x * 128;
    int tx = tid & 15, ty = tid >> 4;

    float acc[8][8];
#pragma unroll
    for (int i = 0; i < 8; i++)
#pragma unroll
        for (int j = 0; j < 8; j++) acc[i][j] = 0.f;

    for (int k0 = 0; k0 < K; k0 += 16) {
#pragma unroll
        for (int i = 0; i < 2; i++) {             // A tile: 128 rows x 16 k (transposed store)
            int idx = tid + i * 256;
            int row = idx >> 2, k4 = idx & 3;
            float4 a = *(const float4*)(A + (size_t)(m0 + row) * K + k0 + k4 * 4);
            As[k4 * 4 + 0][row] = a.x;
            As[k4 * 4 + 1][row] = a.y;
            As[k4 * 4 + 2][row] = a.z;
            As[k4 * 4 + 3][row] = a.w;
        }
#pragma unroll
        for (int i = 0; i < 2; i++) {             // B tile: 16 k x 128 cols
            int idx = tid + i * 256;
            int row = idx >> 5, c4 = idx & 31;
            *(float4*)(&Bs[row][c4 * 4]) =
                *(const float4*)(B + (size_t)(k0 + row) * N + n0 + c4 * 4);
        }
        __syncthreads();

#pragma unroll
        for (int kk = 0; kk < 16; kk++) {
            float af[8], bf[8];
            *(float4*)(af)     = *(const float4*)(&As[kk][ty * 8]);
            *(float4*)(af + 4) = *(const float4*)(&As[kk][ty * 8 + 4]);
            *(float4*)(bf)     = *(const float4*)(&Bs[kk][tx * 8]);
            *(float4*)(bf + 4) = *(const float4*)(&Bs[kk][tx * 8 + 4]);
#pragma unroll
            for (int i = 0; i < 8; i++)
#pragma unroll
                for (int j = 0; j < 8; j++) acc[i][j] = fmaf(af[i], bf[j], acc[i][j]);
        }
        __syncthreads();
    }

#pragma unroll
    for (int i = 0; i < 8; i++) {
        int row = m0 + ty * 8 + i;
        size_t rowBase;
        if (EPI == 2) rowBase = (size_t)mapFlat(row) * CDIM;
        else          rowBase = (size_t)row * N;
#pragma unroll
        for (int j = 0; j < 8; j++) {
            int col = n0 + tx * 8 + j;
            float v = acc[i][j] + bias[col];
            if (EPI == 1) v = 0.5f * v * (1.0f + erff(v * 0.70710678118654752f));
            if (EPI == 2 || EPI == 3) v += resid[rowBase + col];
            C[rowBase + col] = v;
        }
    }
}

// ---------------------------------------------------------------------------
// Attention: one block per (window, head). 64 tokens x 64 dims, fp32, smem.
// qkv layout per row (1536): [q: h*64+d | k: 512+h*64+d | v: 1024+h*64+d]
// ---------------------------------------------------------------------------
#define AP 65   // smem row pitch (65 % 32 == 1 -> conflict-free column walks)

__global__ void __launch_bounds__(256) attn_kernel(
    const float* __restrict__ qkv, float* __restrict__ out)
{
    extern __shared__ float sm[];
    float* q  = sm;
    float* ks = sm + 64 * AP;
    float* vs = sm + 2 * 64 * AP;
    float* sc = sm + 3 * 64 * AP;

    int win = blockIdx.x >> 3, head = blockIdx.x & 7;
    int tid = threadIdx.x;
    const float* base = qkv + (size_t)win * 64 * QKVDIM + head * 64;

#pragma unroll
    for (int i = 0; i < 16; i++) {
        int idx = tid + i * 256;
        int n = idx >> 6, d = idx & 63;
        size_t ro = (size_t)n * QKVDIM + d;
        q [n * AP + d] = base[ro];
        ks[n * AP + d] = base[ro + 512];
        vs[n * AP + d] = base[ro + 1024];
    }
    __syncthreads();

    // logits = (q @ k^T) * 1/8
#pragma unroll 4
    for (int i = 0; i < 16; i++) {
        int idx = tid + i * 256;
        int n = idx >> 6, m = idx & 63;
        float a = 0.f;
#pragma unroll
        for (int d = 0; d < 64; d++) a = fmaf(q[n * AP + d], ks[m * AP + d], a);
        sc[n * AP + m] = a * 0.125f;
    }
    __syncthreads();

    // softmax: one thread per row
    if (tid < 64) {
        float mx = -1e30f;
        for (int m = 0; m < 64; m++) mx = fmaxf(mx, sc[tid * AP + m]);
        float s = 0.f;
        for (int m = 0; m < 64; m++) {
            float e = expf(sc[tid * AP + m] - mx);
            sc[tid * AP + m] = e;
            s += e;
        }
        float inv = 1.0f / s;
        for (int m = 0; m < 64; m++) sc[tid * AP + m] *= inv;
    }
    __syncthreads();

    // out = attn @ v
#pragma unroll 4
    for (int i = 0; i < 16; i++) {
        int idx = tid + i * 256;
        int n = idx >> 6, d = idx & 63;
        float a = 0.f;
#pragma unroll
        for (int m = 0; m < 64; m++) a = fmaf(sc[n * AP + m], vs[m * AP + d], a);
        out[((size_t)win * 64 + n) * CDIM + head * 64 + d] = a;
    }
}

#define ATTN_SMEM (4 * 64 * AP * (int)sizeof(float))

// ---------------------------------------------------------------------------
extern "C" void kernel_launch(void* const* d_in, const int* in_sizes, int n_in,
                              void* d_out, int out_size)
{
    const float* x      = (const float*)d_in[0];
    const float* ln1_g  = (const float*)d_in[1];
    const float* ln1_b  = (const float*)d_in[2];
    const float* qkv_w  = (const float*)d_in[3];
    const float* qkv_b  = (const float*)d_in[4];
    const float* proj_w = (const float*)d_in[5];
    const float* proj_b = (const float*)d_in[6];
    const float* ln2_g  = (const float*)d_in[7];
    const float* ln2_b  = (const float*)d_in[8];
    const float* ffn_w1 = (const float*)d_in[9];
    const float* ffn_b1 = (const float*)d_in[10];
    const float* ffn_w2 = (const float*)d_in[11];
    const float* ffn_b2 = (const float*)d_in[12];
    float* out = (float*)d_out;

    float *p_h, *p_qkv, *p_attn, *p_xo, *p_h2, *p_hid;
    cudaGetSymbolAddress((void**)&p_h,    g_h);
    cudaGetSymbolAddress((void**)&p_qkv,  g_qkv);
    cudaGetSymbolAddress((void**)&p_attn, g_attn);
    cudaGetSymbolAddress((void**)&p_xo,   g_xo);
    cudaGetSymbolAddress((void**)&p_h2,   g_h2);
    cudaGetSymbolAddress((void**)&p_hid,  g_hid);

    cudaFuncSetAttribute(attn_kernel,
                         cudaFuncAttributeMaxDynamicSharedMemorySize, ATTN_SMEM);

    // 1. shift + window partition + LN1
    ln_kernel<true><<<NROWS / 8, 256>>>(x, ln1_g, ln1_b, p_h);

    // 2. QKV GEMM  (65536 x 1536 x 512)
    gemm_kernel<0><<<dim3(QKVDIM / 128, NROWS / 128), 256>>>(
        p_h, qkv_w, qkv_b, nullptr, p_qkv, NROWS, QKVDIM, CDIM);

    // 3. windowed attention (1024 windows x 8 heads)
    attn_kernel<<<1024 * 8, 256, ATTN_SMEM>>>(p_qkv, p_attn);

    // 4. proj GEMM + residual + window-reverse/unshift scatter (65536x512x512)
    gemm_kernel<2><<<dim3(CDIM / 128, NROWS / 128), 256>>>(
        p_attn, proj_w, proj_b, x, p_xo, NROWS, CDIM, CDIM);

    // 5. LN2
    ln_kernel<false><<<NROWS / 8, 256>>>(p_xo, ln2_g, ln2_b, p_h2);

    // 6. FFN1 GEMM + exact GELU (65536 x 2048 x 512)
    gemm_kernel<1><<<dim3(HIDDIM / 128, NROWS / 128), 256>>>(
        p_h2, ffn_w1, ffn_b1, nullptr, p_hid, NROWS, HIDDIM, CDIM);

    // 7. FFN2 GEMM + residual -> d_out (65536 x 512 x 2048)
    gemm_kernel<3><<<dim3(CDIM / 128, NROWS / 128), 256>>>(
        p_hid, ffn_w2, ffn_b2, p_xo, out, NROWS, CDIM, HIDDIM);
}

// round 5
// speedup vs baseline: 2.5818x; 2.5818x over previous
#include <cuda_runtime.h>
#include <math.h>
#include <stdint.h>

// ---------------------------------------------------------------------------
// Windowed 3D attention block — tf32 mma.sync (m16n8k8) tensor-core GEMMs.
// (tcgen05 is rejected by the harness's compute_103 PTX target; mma.sync is
// the baseline-ISA tensor path.)
// ---------------------------------------------------------------------------

#define NROWS   65536
#define CDIM    512
#define QKVDIM  1536
#define HIDDIM  2048

__device__ float g_h   [ (size_t)NROWS * CDIM  ];
__device__ float g_qkv [ (size_t)NROWS * QKVDIM];
__device__ float g_attn[ (size_t)NROWS * CDIM  ];
__device__ float g_xo  [ (size_t)NROWS * CDIM  ];
__device__ float g_h2  [ (size_t)NROWS * CDIM  ];
__device__ float g_hid [ (size_t)NROWS * HIDDIM];
// tf32-rounded weight copies (natural [K][N] layout)
__device__ float g_qkvw [(size_t)CDIM * QKVDIM];
__device__ float g_projw[(size_t)CDIM * CDIM  ];
__device__ float g_w1   [(size_t)CDIM * HIDDIM];
__device__ float g_w2   [(size_t)HIDDIM * CDIM];

// ---------------------------------------------------------------------------
__device__ __forceinline__ float cvt_tf32(float x) {
    uint32_t u = __float_as_uint(x);
    asm volatile("cvt.rn.tf32.f32 %0, %1;" : "=r"(u) : "r"(u));
    return __uint_as_float(u);
}

__device__ __forceinline__ uint32_t smem_u32(const void* p) {
    uint32_t a;
    asm("{ .reg .u64 t; cvta.to.shared.u64 t, %1; cvt.u32.u64 %0, t; }"
        : "=r"(a) : "l"(p));
    return a;
}

__device__ __forceinline__ void cp16(void* dst, const void* src) {
    asm volatile("cp.async.cg.shared.global [%0], [%1], 16;"
                 :: "r"(smem_u32(dst)), "l"(src));
}
#define CP_COMMIT() asm volatile("cp.async.commit_group;" ::: "memory")
template <int N>
__device__ __forceinline__ void cp_wait() {
    asm volatile("cp.async.wait_group %0;" :: "n"(N) : "memory");
}

#define MMA_TF32(d, a, b)                                                      \
    asm volatile(                                                              \
        "mma.sync.aligned.m16n8k8.row.col.f32.tf32.tf32.f32 "                  \
        "{%0,%1,%2,%3}, {%4,%5,%6,%7}, {%8,%9}, {%0,%1,%2,%3};"                \
        : "+f"((d)[0]), "+f"((d)[1]), "+f"((d)[2]), "+f"((d)[3])               \
        : "r"((a)[0]), "r"((a)[1]), "r"((a)[2]), "r"((a)[3]),                  \
          "r"((b)[0]), "r"((b)[1]))

// ---------------------------------------------------------------------------
__device__ __forceinline__ int mapFlat(int r) {
    int win = r >> 6, t = r & 63;
    int b  = win >> 9;
    int wd = (win >> 6) & 7, wh = (win >> 3) & 7, ww = win & 7;
    int td = t >> 4, th = (t >> 2) & 3, tw = t & 3;
    int d0 = (wd * 4 + td + 2) & 31;
    int h0 = (wh * 4 + th + 2) & 31;
    int w0 = (ww * 4 + tw + 2) & 31;
    return ((b * 32 + d0) * 32 + h0) * 32 + w0;
}

// ---------------------------------------------------------------------------
// Elementwise tf32 round (weights)
// ---------------------------------------------------------------------------
__global__ void cvt_copy(const float* __restrict__ in, float* __restrict__ out) {
    size_t i = ((size_t)blockIdx.x * 256 + threadIdx.x) * 4;
    float4 v = *(const float4*)(in + i);
    v.x = cvt_tf32(v.x); v.y = cvt_tf32(v.y);
    v.z = cvt_tf32(v.z); v.w = cvt_tf32(v.w);
    *(float4*)(out + i) = v;
}

// ---------------------------------------------------------------------------
// LayerNorm (tf32-rounded output; fused shift/window gather when MAPPED)
// ---------------------------------------------------------------------------
template <bool MAPPED>
__global__ void __launch_bounds__(256) ln_kernel(
    const float* __restrict__ in, const float* __restrict__ gam,
    const float* __restrict__ bet, float* __restrict__ out)
{
    int warp = threadIdx.x >> 5, lane = threadIdx.x & 31;
    int r = blockIdx.x * 8 + warp;
    int src = MAPPED ? mapFlat(r) : r;

    const float4* ip = (const float4*)(in + (size_t)src * CDIM);
    float4 vals[4];
    float s = 0.f, sq = 0.f;
#pragma unroll
    for (int w = 0; w < 4; w++) {
        float4 v = ip[w * 32 + lane];
        vals[w] = v;
        s  += v.x + v.y + v.z + v.w;
        sq += v.x * v.x + v.y * v.y + v.z * v.z + v.w * v.w;
    }
#pragma unroll
    for (int o = 16; o > 0; o >>= 1) {
        s  += __shfl_xor_sync(0xffffffffu, s,  o);
        sq += __shfl_xor_sync(0xffffffffu, sq, o);
    }
    float m  = s * (1.0f / CDIM);
    float var = sq * (1.0f / CDIM) - m * m;
    float rs = rsqrtf(var + 1e-5f);

    float4* op = (float4*)(out + (size_t)r * CDIM);
    const float4* gp = (const float4*)gam;
    const float4* bp = (const float4*)bet;
#pragma unroll
    for (int w = 0; w < 4; w++) {
        int c4 = w * 32 + lane;
        float4 g = gp[c4], b = bp[c4], x = vals[w], o4;
        o4.x = cvt_tf32((x.x - m) * rs * g.x + b.x);
        o4.y = cvt_tf32((x.y - m) * rs * g.y + b.y);
        o4.z = cvt_tf32((x.z - m) * rs * g.z + b.z);
        o4.w = cvt_tf32((x.w - m) * rs * g.w + b.w);
        op[c4] = o4;
    }
}

// ---------------------------------------------------------------------------
// tf32 mma.sync GEMM: C[M,N] = A[M,K] @ B[K,N]  (block 128x256, BK=32)
// 8 warps (2M x 4N), warp tile 64x64 = 4x8 m16n8k8 fragments.
// EPI 0: +bias   EPI 1: tf32(gelu(+bias))
// EPI 2: mapFlat scatter +resid+bias   EPI 3: +resid+bias
// ---------------------------------------------------------------------------
#define BM 128
#define BN 256
#define BK 32
#define ASTR 36    // As row stride (floats): 4m+k banks all distinct
#define BSTR 264   // Bs row stride (floats): 8k+n banks all distinct
#define A_FLOATS (BM * ASTR)
#define B_FLOATS (BK * BSTR)

template <int EPI>
__global__ void __launch_bounds__(256, 1) tc_gemm(
    const float* __restrict__ A, const float* __restrict__ B,
    const float* __restrict__ bias, const float* __restrict__ resid,
    float* __restrict__ C, int M, int N, int K)
{
    extern __shared__ float smf[];
    float* Asm[2] = { smf, smf + A_FLOATS };
    float* Bsm[2] = { smf + 2 * A_FLOATS, smf + 2 * A_FLOATS + B_FLOATS };

    int tid = threadIdx.x;
    int wid = tid >> 5, lane = tid & 31;
    int wm = wid >> 2, wn = wid & 3;           // warp grid 2 x 4
    int lr = lane >> 2, lc = lane & 3;         // groupID / threadInGroup
    int m0 = blockIdx.y * BM, n0 = blockIdx.x * BN;

    float acc[4][8][4];
#pragma unroll
    for (int i = 0; i < 4; i++)
#pragma unroll
        for (int j = 0; j < 8; j++)
#pragma unroll
            for (int q = 0; q < 4; q++) acc[i][j][q] = 0.f;

    const int NCH = K >> 5;

    auto issue = [&](int it) {
        int s = it & 1;
        const float* Ab = A + (size_t)m0 * K + it * BK;
#pragma unroll
        for (int i = 0; i < 4; i++) {          // A: 128 x 32 f32
            int idx = i * 256 + tid;
            int row = idx >> 3, kq = idx & 7;
            cp16(Asm[s] + row * ASTR + kq * 4, Ab + (size_t)row * K + kq * 4);
        }
        const float* Bb = B + (size_t)it * BK * N + n0;
#pragma unroll
        for (int i = 0; i < 8; i++) {          // B: 32 x 256 f32
            int idx = i * 256 + tid;
            int row = idx >> 6, nq = idx & 63;
            cp16(Bsm[s] + row * BSTR + nq * 4, Bb + (size_t)row * N + nq * 4);
        }
        CP_COMMIT();
    };

    issue(0);

    for (int it = 0; it < NCH; it++) {
        if (it + 1 < NCH) { issue(it + 1); cp_wait<1>(); }
        else              { cp_wait<0>(); }
        __syncthreads();

        const float* As0 = Asm[it & 1];
        const float* Bs0 = Bsm[it & 1];
#pragma unroll
        for (int ks = 0; ks < 4; ks++) {
            int k = ks * 8;
            uint32_t a[4][4];
#pragma unroll
            for (int mi = 0; mi < 4; mi++) {
                const float* p = As0 + (wm * 64 + mi * 16 + lr) * ASTR + k + lc;
                a[mi][0] = __float_as_uint(p[0]);
                a[mi][1] = __float_as_uint(p[8 * ASTR]);
                a[mi][2] = __float_as_uint(p[4]);
                a[mi][3] = __float_as_uint(p[8 * ASTR + 4]);
            }
            uint32_t b[8][2];
#pragma unroll
            for (int ni = 0; ni < 8; ni++) {
                const float* p = Bs0 + (k + lc) * BSTR + wn * 64 + ni * 8 + lr;
                b[ni][0] = __float_as_uint(p[0]);
                b[ni][1] = __float_as_uint(p[4 * BSTR]);
            }
#pragma unroll
            for (int mi = 0; mi < 4; mi++)
#pragma unroll
                for (int ni = 0; ni < 8; ni++)
                    MMA_TF32(acc[mi][ni], a[mi], b[ni]);
        }
        __syncthreads();
    }

    // Epilogue. c0,c1: (row=lr, col=2*lc,+1); c2,c3: row+8.
#pragma unroll
    for (int mi = 0; mi < 4; mi++) {
        int r0 = m0 + wm * 64 + mi * 16 + lr;
        size_t rb0, rb1;
        if (EPI == 2) { rb0 = (size_t)mapFlat(r0) * CDIM;
                        rb1 = (size_t)mapFlat(r0 + 8) * CDIM; }
        else          { rb0 = (size_t)r0 * N; rb1 = rb0 + (size_t)8 * N; }
#pragma unroll
        for (int ni = 0; ni < 8; ni++) {
            int c = n0 + wn * 64 + ni * 8 + lc * 2;
            float2 bs = *(const float2*)(bias + c);
            float v0 = acc[mi][ni][0] + bs.x, v1 = acc[mi][ni][1] + bs.y;
            float v2 = acc[mi][ni][2] + bs.x, v3 = acc[mi][ni][3] + bs.y;
            if (EPI == 1) {
                v0 = cvt_tf32(0.5f * v0 * (1.0f + erff(v0 * 0.70710678118654752f)));
                v1 = cvt_tf32(0.5f * v1 * (1.0f + erff(v1 * 0.70710678118654752f)));
                v2 = cvt_tf32(0.5f * v2 * (1.0f + erff(v2 * 0.70710678118654752f)));
                v3 = cvt_tf32(0.5f * v3 * (1.0f + erff(v3 * 0.70710678118654752f)));
            }
            if (EPI == 2 || EPI == 3) {
                float2 r0v = *(const float2*)(resid + rb0 + c);
                float2 r1v = *(const float2*)(resid + rb1 + c);
                v0 += r0v.x; v1 += r0v.y; v2 += r1v.x; v3 += r1v.y;
            }
            *(float2*)(C + rb0 + c) = make_float2(v0, v1);
            *(float2*)(C + rb1 + c) = make_float2(v2, v3);
        }
    }
}

#define GEMM_SMEM ((2 * A_FLOATS + 2 * B_FLOATS) * (int)sizeof(float))

// ---------------------------------------------------------------------------
// Attention: one block per (window, head). 64x64, fp32 in smem.
// ---------------------------------------------------------------------------
#define AP 65

__global__ void __launch_bounds__(256) attn_kernel(
    const float* __restrict__ qkv, float* __restrict__ out)
{
    extern __shared__ float smf[];
    float* q  = smf;
    float* ks = smf + 64 * AP;
    float* vs = smf + 2 * 64 * AP;
    float* sc = smf + 3 * 64 * AP;

    int win = blockIdx.x >> 3, head = blockIdx.x & 7;
    int tid = threadIdx.x;
    const float* base = qkv + (size_t)win * 64 * QKVDIM + head * 64;

#pragma unroll
    for (int i = 0; i < 16; i++) {
        int idx = tid + i * 256;
        int n = idx >> 6, d = idx & 63;
        size_t ro = (size_t)n * QKVDIM + d;
        q [n * AP + d] = base[ro];
        ks[n * AP + d] = base[ro + 512];
        vs[n * AP + d] = base[ro + 1024];
    }
    __syncthreads();

#pragma unroll 4
    for (int i = 0; i < 16; i++) {
        int idx = tid + i * 256;
        int n = idx >> 6, m = idx & 63;
        float a = 0.f;
#pragma unroll
        for (int d = 0; d < 64; d++) a = fmaf(q[n * AP + d], ks[m * AP + d], a);
        sc[n * AP + m] = a * 0.125f;
    }
    __syncthreads();

    if (tid < 64) {
        float mx = -1e30f;
        for (int m = 0; m < 64; m++) mx = fmaxf(mx, sc[tid * AP + m]);
        float s = 0.f;
        for (int m = 0; m < 64; m++) {
            float e = expf(sc[tid * AP + m] - mx);
            sc[tid * AP + m] = e;
            s += e;
        }
        float inv = 1.0f / s;
        for (int m = 0; m < 64; m++) sc[tid * AP + m] *= inv;
    }
    __syncthreads();

#pragma unroll 4
    for (int i = 0; i < 16; i++) {
        int idx = tid + i * 256;
        int n = idx >> 6, d = idx & 63;
        float a = 0.f;
#pragma unroll
        for (int m = 0; m < 64; m++) a = fmaf(sc[n * AP + m], vs[m * AP + d], a);
        out[((size_t)win * 64 + n) * CDIM + head * 64 + d] = cvt_tf32(a);
    }
}

#define ATTN_SMEM (4 * 64 * AP * (int)sizeof(float))

// ---------------------------------------------------------------------------
extern "C" void kernel_launch(void* const* d_in, const int* in_sizes, int n_in,
                              void* d_out, int out_size)
{
    const float* x      = (const float*)d_in[0];
    const float* ln1_g  = (const float*)d_in[1];
    const float* ln1_b  = (const float*)d_in[2];
    const float* qkv_w  = (const float*)d_in[3];
    const float* qkv_b  = (const float*)d_in[4];
    const float* proj_w = (const float*)d_in[5];
    const float* proj_b = (const float*)d_in[6];
    const float* ln2_g  = (const float*)d_in[7];
    const float* ln2_b  = (const float*)d_in[8];
    const float* ffn_w1 = (const float*)d_in[9];
    const float* ffn_b1 = (const float*)d_in[10];
    const float* ffn_w2 = (const float*)d_in[11];
    const float* ffn_b2 = (const float*)d_in[12];
    float* out = (float*)d_out;

    float *p_h, *p_qkv, *p_attn, *p_xo, *p_h2, *p_hid;
    float *p_qkvw, *p_projw, *p_w1, *p_w2;
    cudaGetSymbolAddress((void**)&p_h,    g_h);
    cudaGetSymbolAddress((void**)&p_qkv,  g_qkv);
    cudaGetSymbolAddress((void**)&p_attn, g_attn);
    cudaGetSymbolAddress((void**)&p_xo,   g_xo);
    cudaGetSymbolAddress((void**)&p_h2,   g_h2);
    cudaGetSymbolAddress((void**)&p_hid,  g_hid);
    cudaGetSymbolAddress((void**)&p_qkvw, g_qkvw);
    cudaGetSymbolAddress((void**)&p_projw,g_projw);
    cudaGetSymbolAddress((void**)&p_w1,   g_w1);
    cudaGetSymbolAddress((void**)&p_w2,   g_w2);

    cudaFuncSetAttribute(attn_kernel,
                         cudaFuncAttributeMaxDynamicSharedMemorySize, ATTN_SMEM);
    cudaFuncSetAttribute(tc_gemm<0>, cudaFuncAttributeMaxDynamicSharedMemorySize, GEMM_SMEM);
    cudaFuncSetAttribute(tc_gemm<1>, cudaFuncAttributeMaxDynamicSharedMemorySize, GEMM_SMEM);
    cudaFuncSetAttribute(tc_gemm<2>, cudaFuncAttributeMaxDynamicSharedMemorySize, GEMM_SMEM);
    cudaFuncSetAttribute(tc_gemm<3>, cudaFuncAttributeMaxDynamicSharedMemorySize, GEMM_SMEM);

    // 0. tf32-round the weights
    cvt_copy<<<(CDIM * QKVDIM) / 1024, 256>>>(qkv_w,  p_qkvw);
    cvt_copy<<<(CDIM * CDIM)   / 1024, 256>>>(proj_w, p_projw);
    cvt_copy<<<(CDIM * HIDDIM) / 1024, 256>>>(ffn_w1, p_w1);
    cvt_copy<<<(HIDDIM * CDIM) / 1024, 256>>>(ffn_w2, p_w2);

    // 1. shift + window partition + LN1
    ln_kernel<true><<<NROWS / 8, 256>>>(x, ln1_g, ln1_b, p_h);

    // 2. QKV GEMM (65536 x 1536 x 512)
    tc_gemm<0><<<dim3(QKVDIM / BN, NROWS / BM), 256, GEMM_SMEM>>>(
        p_h, p_qkvw, qkv_b, nullptr, p_qkv, NROWS, QKVDIM, CDIM);

    // 3. windowed attention
    attn_kernel<<<1024 * 8, 256, ATTN_SMEM>>>(p_qkv, p_attn);

    // 4. proj GEMM + residual + window-reverse scatter (65536 x 512 x 512)
    tc_gemm<2><<<dim3(CDIM / BN, NROWS / BM), 256, GEMM_SMEM>>>(
        p_attn, p_projw, proj_b, x, p_xo, NROWS, CDIM, CDIM);

    // 5. LN2
    ln_kernel<false><<<NROWS / 8, 256>>>(p_xo, ln2_g, ln2_b, p_h2);

    // 6. FFN1 GEMM + GELU (65536 x 2048 x 512)
    tc_gemm<1><<<dim3(HIDDIM / BN, NROWS / BM), 256, GEMM_SMEM>>>(
        p_h2, p_w1, ffn_b1, nullptr, p_hid, NROWS, HIDDIM, CDIM);

    // 7. FFN2 GEMM + residual -> out (65536 x 512 x 2048)
    tc_gemm<3><<<dim3(CDIM / BN, NROWS / BM), 256, GEMM_SMEM>>>(
        p_hid, p_w2, ffn_b2, p_xo, out, NROWS, CDIM, HIDDIM);
}

// round 6
// speedup vs baseline: 3.5365x; 1.3698x over previous
#include <cuda_runtime.h>
#include <cuda_fp16.h>
#include <math.h>
#include <stdint.h>

// ---------------------------------------------------------------------------
// Windowed 3D attention block — fp16 mma.sync (m16n8k16) tensor-core GEMMs.
// fp16 has the same 10-bit mantissa as tf32 (values here are small-range),
// but legacy HMMA fp16 runs at 2x the tf32 rate and halves operand traffic.
// Residual paths stay fp32.
// ---------------------------------------------------------------------------

#define NROWS   65536
#define CDIM    512
#define QKVDIM  1536
#define HIDDIM  2048

__device__ __half g_h   [ (size_t)NROWS * CDIM  ];
__device__ __half g_qkv [ (size_t)NROWS * QKVDIM];
__device__ __half g_attn[ (size_t)NROWS * CDIM  ];
__device__ float  g_xo  [ (size_t)NROWS * CDIM  ];
__device__ __half g_h2  [ (size_t)NROWS * CDIM  ];
__device__ __half g_hid [ (size_t)NROWS * HIDDIM];
// Transposed half weights: Wt[N][K]
__device__ __half g_qkvw [(size_t)QKVDIM * CDIM];
__device__ __half g_projw[(size_t)CDIM * CDIM  ];
__device__ __half g_w1   [(size_t)HIDDIM * CDIM];
__device__ __half g_w2   [(size_t)CDIM * HIDDIM];

// ---------------------------------------------------------------------------
__device__ __forceinline__ uint32_t smem_u32(const void* p) {
    uint32_t a;
    asm("{ .reg .u64 t; cvta.to.shared.u64 t, %1; cvt.u32.u64 %0, t; }"
        : "=r"(a) : "l"(p));
    return a;
}

__device__ __forceinline__ void cp16(void* dst, const void* src) {
    asm volatile("cp.async.cg.shared.global [%0], [%1], 16;"
                 :: "r"(smem_u32(dst)), "l"(src));
}
#define CP_COMMIT() asm volatile("cp.async.commit_group;" ::: "memory")
template <int N>
__device__ __forceinline__ void cp_wait() {
    asm volatile("cp.async.wait_group %0;" :: "n"(N) : "memory");
}

#define MMA_F16(d, a, b)                                                       \
    asm volatile(                                                              \
        "mma.sync.aligned.m16n8k16.row.col.f32.f16.f16.f32 "                   \
        "{%0,%1,%2,%3}, {%4,%5,%6,%7}, {%8,%9}, {%0,%1,%2,%3};"                \
        : "+f"((d)[0]), "+f"((d)[1]), "+f"((d)[2]), "+f"((d)[3])               \
        : "r"((a)[0]), "r"((a)[1]), "r"((a)[2]), "r"((a)[3]),                  \
          "r"((b)[0]), "r"((b)[1]))

// ---------------------------------------------------------------------------
__device__ __forceinline__ int mapFlat(int r) {
    int win = r >> 6, t = r & 63;
    int b  = win >> 9;
    int wd = (win >> 6) & 7, wh = (win >> 3) & 7, ww = win & 7;
    int td = t >> 4, th = (t >> 2) & 3, tw = t & 3;
    int d0 = (wd * 4 + td + 2) & 31;
    int h0 = (wh * 4 + th + 2) & 31;
    int w0 = (ww * 4 + tw + 2) & 31;
    return ((b * 32 + d0) * 32 + h0) * 32 + w0;
}

// ---------------------------------------------------------------------------
// Weight transpose: float [K][N] -> half [N][K]
// ---------------------------------------------------------------------------
__global__ void transpose_h(const float* __restrict__ in, __half* __restrict__ out,
                            int K, int N)
{
    __shared__ float t[32][33];
    int n0 = blockIdx.x * 32, k0 = blockIdx.y * 32;
    int x = threadIdx.x, y = threadIdx.y;
#pragma unroll
    for (int i = 0; i < 4; i++)
        t[y + i * 8][x] = in[(size_t)(k0 + y + i * 8) * N + n0 + x];
    __syncthreads();
#pragma unroll
    for (int i = 0; i < 4; i++)
        out[(size_t)(n0 + y + i * 8) * K + k0 + x] = __float2half_rn(t[x][y + i * 8]);
}

// ---------------------------------------------------------------------------
// LayerNorm (fp32 in -> half out; fused shift/window gather when MAPPED)
// ---------------------------------------------------------------------------
template <bool MAPPED>
__global__ void __launch_bounds__(256) ln_kernel(
    const float* __restrict__ in, const float* __restrict__ gam,
    const float* __restrict__ bet, __half* __restrict__ out)
{
    int warp = threadIdx.x >> 5, lane = threadIdx.x & 31;
    int r = blockIdx.x * 8 + warp;
    int src = MAPPED ? mapFlat(r) : r;

    const float4* ip = (const float4*)(in + (size_t)src * CDIM);
    float4 vals[4];
    float s = 0.f, sq = 0.f;
#pragma unroll
    for (int w = 0; w < 4; w++) {
        float4 v = ip[w * 32 + lane];
        vals[w] = v;
        s  += v.x + v.y + v.z + v.w;
        sq += v.x * v.x + v.y * v.y + v.z * v.z + v.w * v.w;
    }
#pragma unroll
    for (int o = 16; o > 0; o >>= 1) {
        s  += __shfl_xor_sync(0xffffffffu, s,  o);
        sq += __shfl_xor_sync(0xffffffffu, sq, o);
    }
    float m  = s * (1.0f / CDIM);
    float var = sq * (1.0f / CDIM) - m * m;
    float rs = rsqrtf(var + 1e-5f);

    __half2* op = (__half2*)(out + (size_t)r * CDIM);
    const float4* gp = (const float4*)gam;
    const float4* bp = (const float4*)bet;
#pragma unroll
    for (int w = 0; w < 4; w++) {
        int c4 = w * 32 + lane;
        float4 g = gp[c4], b = bp[c4], x = vals[w];
        op[c4 * 2]     = __floats2half2_rn((x.x - m) * rs * g.x + b.x,
                                           (x.y - m) * rs * g.y + b.y);
        op[c4 * 2 + 1] = __floats2half2_rn((x.z - m) * rs * g.z + b.z,
                                           (x.w - m) * rs * g.w + b.w);
    }
}

// ---------------------------------------------------------------------------
// fp16 mma.sync GEMM: C[M,N] = A[M,K] @ Bt[N,K]^T  (block 128x256, BK=32,
// 3-stage cp.async). 8 warps (2M x 4N), warp tile 64x64 = 4x8 m16n8k16.
// EPI 0: half out, +bias      EPI 1: half out, gelu(+bias)
// EPI 2: float out, mapFlat scatter +resid+bias   EPI 3: float out, +resid+bias
// ---------------------------------------------------------------------------
#define BM 128
#define BN 256
#define BK 32
#define ASTRH 40                 // halfs per A smem row (20 words -> distinct banks)
#define BSTRH 40
#define A_HALFS (BM * ASTRH)     // 5120
#define B_HALFS (BN * BSTRH)     // 10240
#define STAGES 3
#define GEMM_SMEM (STAGES * (A_HALFS + B_HALFS) * 2)

template <int EPI, typename OutT>
__global__ void __launch_bounds__(256, 1) tc_gemm(
    const __half* __restrict__ A, const __half* __restrict__ Bt,
    const float* __restrict__ bias, const float* __restrict__ resid,
    OutT* __restrict__ C, int M, int N, int K)
{
    extern __shared__ __half smh[];
    __half* Asm[STAGES];
    __half* Bsm[STAGES];
#pragma unroll
    for (int s = 0; s < STAGES; s++) {
        Asm[s] = smh + s * A_HALFS;
        Bsm[s] = smh + STAGES * A_HALFS + s * B_HALFS;
    }

    int tid = threadIdx.x;
    int wid = tid >> 5, lane = tid & 31;
    int wm = wid >> 2, wn = wid & 3;
    int lr = lane >> 2, lc = lane & 3;
    int m0 = blockIdx.y * BM, n0 = blockIdx.x * BN;

    float acc[4][8][4];
#pragma unroll
    for (int i = 0; i < 4; i++)
#pragma unroll
        for (int j = 0; j < 8; j++)
#pragma unroll
            for (int q = 0; q < 4; q++) acc[i][j][q] = 0.f;

    const int NCH = K >> 5;

    auto issue = [&](int it) {
        int s = it % STAGES;
        const __half* Ab = A + (size_t)m0 * K + it * BK;
#pragma unroll
        for (int i = 0; i < 2; i++) {          // A: 128 x 32 halfs (512 chunks)
            int idx = i * 256 + tid;
            int row = idx >> 2, kq = idx & 3;
            cp16(Asm[s] + row * ASTRH + kq * 8, Ab + (size_t)row * K + kq * 8);
        }
        const __half* Bb = Bt + (size_t)n0 * K + it * BK;
#pragma unroll
        for (int i = 0; i < 4; i++) {          // B: 256 x 32 halfs (1024 chunks)
            int idx = i * 256 + tid;
            int row = idx >> 2, kq = idx & 3;
            cp16(Bsm[s] + row * BSTRH + kq * 8, Bb + (size_t)row * K + kq * 8);
        }
        CP_COMMIT();
    };

    issue(0);
    issue(1);

    for (int it = 0; it < NCH; it++) {
        if (it + 1 < NCH) cp_wait<1>();
        else              cp_wait<0>();
        __syncthreads();
        if (it + 2 < NCH) issue(it + 2);

        const __half* As0 = Asm[it % STAGES];
        const __half* Bs0 = Bsm[it % STAGES];
#pragma unroll
        for (int ks = 0; ks < 2; ks++) {
            int k = ks * 16;
            uint32_t a[4][4];
#pragma unroll
            for (int mi = 0; mi < 4; mi++) {
                const __half* p = As0 + (wm * 64 + mi * 16 + lr) * ASTRH + k + lc * 2;
                a[mi][0] = *(const uint32_t*)(p);
                a[mi][1] = *(const uint32_t*)(p + 8 * ASTRH);
                a[mi][2] = *(const uint32_t*)(p + 8);
                a[mi][3] = *(const uint32_t*)(p + 8 * ASTRH + 8);
            }
            uint32_t b[8][2];
#pragma unroll
            for (int ni = 0; ni < 8; ni++) {
                const __half* p = Bs0 + (wn * 64 + ni * 8 + lr) * BSTRH + k + lc * 2;
                b[ni][0] = *(const uint32_t*)(p);
                b[ni][1] = *(const uint32_t*)(p + 8);
            }
#pragma unroll
            for (int mi = 0; mi < 4; mi++)
#pragma unroll
                for (int ni = 0; ni < 8; ni++)
                    MMA_F16(acc[mi][ni], a[mi], b[ni]);
        }
        __syncthreads();
    }

    // Epilogue. c0,c1: (row=lr, col 2lc,2lc+1); c2,c3: row+8.
#pragma unroll
    for (int mi = 0; mi < 4; mi++) {
        int r0 = m0 + wm * 64 + mi * 16 + lr;
        size_t rb0, rb1;
        if (EPI == 2) { rb0 = (size_t)mapFlat(r0) * CDIM;
                        rb1 = (size_t)mapFlat(r0 + 8) * CDIM; }
        else          { rb0 = (size_t)r0 * N; rb1 = rb0 + (size_t)8 * N; }
#pragma unroll
        for (int ni = 0; ni < 8; ni++) {
            int c = n0 + wn * 64 + ni * 8 + lc * 2;
            float2 bs = *(const float2*)(bias + c);
            float v0 = acc[mi][ni][0] + bs.x, v1 = acc[mi][ni][1] + bs.y;
            float v2 = acc[mi][ni][2] + bs.x, v3 = acc[mi][ni][3] + bs.y;
            if (EPI == 1) {
                v0 = 0.5f * v0 * (1.0f + erff(v0 * 0.70710678118654752f));
                v1 = 0.5f * v1 * (1.0f + erff(v1 * 0.70710678118654752f));
                v2 = 0.5f * v2 * (1.0f + erff(v2 * 0.70710678118654752f));
                v3 = 0.5f * v3 * (1.0f + erff(v3 * 0.70710678118654752f));
            }
            if (EPI == 2 || EPI == 3) {
                float2 r0v = *(const float2*)(resid + rb0 + c);
                float2 r1v = *(const float2*)(resid + rb1 + c);
                v0 += r0v.x; v1 += r0v.y; v2 += r1v.x; v3 += r1v.y;
                float* Cf = (float*)C;
                *(float2*)(Cf + rb0 + c) = make_float2(v0, v1);
                *(float2*)(Cf + rb1 + c) = make_float2(v2, v3);
            } else {
                __half* Ch = (__half*)C;
                *(__half2*)(Ch + rb0 + c) = __floats2half2_rn(v0, v1);
                *(__half2*)(Ch + rb1 + c) = __floats2half2_rn(v2, v3);
            }
        }
    }
}

// ---------------------------------------------------------------------------
// Attention: one block per (window, head). 64x64, fp32 math, half I/O.
// ---------------------------------------------------------------------------
#define AP 65

__global__ void __launch_bounds__(256) attn_kernel(
    const __half* __restrict__ qkv, __half* __restrict__ out)
{
    extern __shared__ float smf[];
    float* q  = smf;
    float* ks = smf + 64 * AP;
    float* vs = smf + 2 * 64 * AP;
    float* sc = smf + 3 * 64 * AP;

    int win = blockIdx.x >> 3, head = blockIdx.x & 7;
    int tid = threadIdx.x;
    const __half* base = qkv + (size_t)win * 64 * QKVDIM + head * 64;

#pragma unroll
    for (int i = 0; i < 8; i++) {              // 2048 half2 per tensor
        int idx = tid + i * 256;
        int n = idx >> 5, d2 = idx & 31;
        size_t ro = (size_t)n * QKVDIM + d2 * 2;
        float2 fq = __half22float2(*(const __half2*)(base + ro));
        float2 fk = __half22float2(*(const __half2*)(base + ro + 512));
        float2 fv = __half22float2(*(const __half2*)(base + ro + 1024));
        q [n * AP + d2 * 2]     = fq.x;  q [n * AP + d2 * 2 + 1] = fq.y;
        ks[n * AP + d2 * 2]     = fk.x;  ks[n * AP + d2 * 2 + 1] = fk.y;
        vs[n * AP + d2 * 2]     = fv.x;  vs[n * AP + d2 * 2 + 1] = fv.y;
    }
    __syncthreads();

#pragma unroll 4
    for (int i = 0; i < 16; i++) {
        int idx = tid + i * 256;
        int n = idx >> 6, m = idx & 63;
        float a = 0.f;
#pragma unroll
        for (int d = 0; d < 64; d++) a = fmaf(q[n * AP + d], ks[m * AP + d], a);
        sc[n * AP + m] = a * 0.125f;
    }
    __syncthreads();

    if (tid < 64) {
        float mx = -1e30f;
        for (int m = 0; m < 64; m++) mx = fmaxf(mx, sc[tid * AP + m]);
        float s = 0.f;
        for (int m = 0; m < 64; m++) {
            float e = expf(sc[tid * AP + m] - mx);
            sc[tid * AP + m] = e;
            s += e;
        }
        float inv = 1.0f / s;
        for (int m = 0; m < 64; m++) sc[tid * AP + m] *= inv;
    }
    __syncthreads();

#pragma unroll 4
    for (int i = 0; i < 16; i++) {
        int idx = tid + i * 256;
        int n = idx >> 6, d = idx & 63;
        float a = 0.f;
#pragma unroll
        for (int m = 0; m < 64; m++) a = fmaf(sc[n * AP + m], vs[m * AP + d], a);
        out[((size_t)win * 64 + n) * CDIM + head * 64 + d] = __float2half_rn(a);
    }
}

#define ATTN_SMEM (4 * 64 * AP * (int)sizeof(float))

// ---------------------------------------------------------------------------
extern "C" void kernel_launch(void* const* d_in, const int* in_sizes, int n_in,
                              void* d_out, int out_size)
{
    const float* x      = (const float*)d_in[0];
    const float* ln1_g  = (const float*)d_in[1];
    const float* ln1_b  = (const float*)d_in[2];
    const float* qkv_w  = (const float*)d_in[3];
    const float* qkv_b  = (const float*)d_in[4];
    const float* proj_w = (const float*)d_in[5];
    const float* proj_b = (const float*)d_in[6];
    const float* ln2_g  = (const float*)d_in[7];
    const float* ln2_b  = (const float*)d_in[8];
    const float* ffn_w1 = (const float*)d_in[9];
    const float* ffn_b1 = (const float*)d_in[10];
    const float* ffn_w2 = (const float*)d_in[11];
    const float* ffn_b2 = (const float*)d_in[12];
    float* out = (float*)d_out;

    __half *p_h, *p_qkv, *p_attn, *p_h2, *p_hid;
    __half *p_qkvw, *p_projw, *p_w1, *p_w2;
    float *p_xo;
    cudaGetSymbolAddress((void**)&p_h,    g_h);
    cudaGetSymbolAddress((void**)&p_qkv,  g_qkv);
    cudaGetSymbolAddress((void**)&p_attn, g_attn);
    cudaGetSymbolAddress((void**)&p_xo,   g_xo);
    cudaGetSymbolAddress((void**)&p_h2,   g_h2);
    cudaGetSymbolAddress((void**)&p_hid,  g_hid);
    cudaGetSymbolAddress((void**)&p_qkvw, g_qkvw);
    cudaGetSymbolAddress((void**)&p_projw,g_projw);
    cudaGetSymbolAddress((void**)&p_w1,   g_w1);
    cudaGetSymbolAddress((void**)&p_w2,   g_w2);

    cudaFuncSetAttribute(attn_kernel,
                         cudaFuncAttributeMaxDynamicSharedMemorySize, ATTN_SMEM);
    cudaFuncSetAttribute((tc_gemm<0, __half>), cudaFuncAttributeMaxDynamicSharedMemorySize, GEMM_SMEM);
    cudaFuncSetAttribute((tc_gemm<1, __half>), cudaFuncAttributeMaxDynamicSharedMemorySize, GEMM_SMEM);
    cudaFuncSetAttribute((tc_gemm<2, float>),  cudaFuncAttributeMaxDynamicSharedMemorySize, GEMM_SMEM);
    cudaFuncSetAttribute((tc_gemm<3, float>),  cudaFuncAttributeMaxDynamicSharedMemorySize, GEMM_SMEM);

    // 0. weight transpose + fp16 convert
    transpose_h<<<dim3(QKVDIM / 32, CDIM / 32),   dim3(32, 8)>>>(qkv_w,  p_qkvw,  CDIM,   QKVDIM);
    transpose_h<<<dim3(CDIM / 32,   CDIM / 32),   dim3(32, 8)>>>(proj_w, p_projw, CDIM,   CDIM);
    transpose_h<<<dim3(HIDDIM / 32, CDIM / 32),   dim3(32, 8)>>>(ffn_w1, p_w1,    CDIM,   HIDDIM);
    transpose_h<<<dim3(CDIM / 32,   HIDDIM / 32), dim3(32, 8)>>>(ffn_w2, p_w2,    HIDDIM, CDIM);

    // 1. shift + window partition + LN1
    ln_kernel<true><<<NROWS / 8, 256>>>(x, ln1_g, ln1_b, p_h);

    // 2. QKV GEMM (65536 x 1536 x 512)
    tc_gemm<0, __half><<<dim3(QKVDIM / BN, NROWS / BM), 256, GEMM_SMEM>>>(
        p_h, p_qkvw, qkv_b, nullptr, p_qkv, NROWS, QKVDIM, CDIM);

    // 3. windowed attention
    attn_kernel<<<1024 * 8, 256, ATTN_SMEM>>>(p_qkv, p_attn);

    // 4. proj GEMM + residual + window-reverse scatter (65536 x 512 x 512)
    tc_gemm<2, float><<<dim3(CDIM / BN, NROWS / BM), 256, GEMM_SMEM>>>(
        p_attn, p_projw, proj_b, x, p_xo, NROWS, CDIM, CDIM);

    // 5. LN2
    ln_kernel<false><<<NROWS / 8, 256>>>(p_xo, ln2_g, ln2_b, p_h2);

    // 6. FFN1 GEMM + GELU (65536 x 2048 x 512)
    tc_gemm<1, __half><<<dim3(HIDDIM / BN, NROWS / BM), 256, GEMM_SMEM>>>(
        p_h2, p_w1, ffn_b1, nullptr, p_hid, NROWS, HIDDIM, CDIM);

    // 7. FFN2 GEMM + residual -> out (65536 x 512 x 2048)
    tc_gemm<3, float><<<dim3(CDIM / BN, NROWS / BM), 256, GEMM_SMEM>>>(
        p_hid, p_w2, ffn_b2, p_xo, out, NROWS, CDIM, HIDDIM);
}

// round 8
// speedup vs baseline: 5.6148x; 1.5877x over previous
#include <cuda_runtime.h>
#include <cuda_fp16.h>
#include <math.h>
#include <stdint.h>

// ---------------------------------------------------------------------------
// Windowed 3D attention block — fp16 mma.sync GEMMs with ldmatrix + BK=64
// 3-stage single-barrier pipeline; tensor-core windowed attention.
// ---------------------------------------------------------------------------

#define NROWS   65536
#define CDIM    512
#define QKVDIM  1536
#define HIDDIM  2048

__device__ __half g_h   [ (size_t)NROWS * CDIM  ];
__device__ __half g_qkv [ (size_t)NROWS * QKVDIM];
__device__ __half g_attn[ (size_t)NROWS * CDIM  ];
__device__ float  g_xo  [ (size_t)NROWS * CDIM  ];
__device__ __half g_h2  [ (size_t)NROWS * CDIM  ];
__device__ __half g_hid [ (size_t)NROWS * HIDDIM];
__device__ __half g_qkvw [(size_t)QKVDIM * CDIM];
__device__ __half g_projw[(size_t)CDIM * CDIM  ];
__device__ __half g_w1   [(size_t)HIDDIM * CDIM];
__device__ __half g_w2   [(size_t)CDIM * HIDDIM];

// ---------------------------------------------------------------------------
__device__ __forceinline__ uint32_t smem_u32(const void* p) {
    uint32_t a;
    asm("{ .reg .u64 t; cvta.to.shared.u64 t, %1; cvt.u32.u64 %0, t; }"
        : "=r"(a) : "l"(p));
    return a;
}

__device__ __forceinline__ void cp16(void* dst, const void* src) {
    asm volatile("cp.async.cg.shared.global [%0], [%1], 16;"
                 :: "r"(smem_u32(dst)), "l"(src));
}
#define CP_COMMIT() asm volatile("cp.async.commit_group;" ::: "memory")
template <int N>
__device__ __forceinline__ void cp_wait() {
    asm volatile("cp.async.wait_group %0;" :: "n"(N) : "memory");
}

#define LDSM4(r0, r1, r2, r3, addr)                                            \
    asm volatile("ldmatrix.sync.aligned.m8n8.x4.shared.b16 {%0,%1,%2,%3}, [%4];" \
        : "=r"(r0), "=r"(r1), "=r"(r2), "=r"(r3) : "r"(addr))

#define LDSM4T(r0, r1, r2, r3, addr)                                           \
    asm volatile("ldmatrix.sync.aligned.m8n8.x4.trans.shared.b16 {%0,%1,%2,%3}, [%4];" \
        : "=r"(r0), "=r"(r1), "=r"(r2), "=r"(r3) : "r"(addr))

#define MMA_F16(d, a, b)                                                       \
    asm volatile(                                                              \
        "mma.sync.aligned.m16n8k16.row.col.f32.f16.f16.f32 "                   \
        "{%0,%1,%2,%3}, {%4,%5,%6,%7}, {%8,%9}, {%0,%1,%2,%3};"                \
        : "+f"((d)[0]), "+f"((d)[1]), "+f"((d)[2]), "+f"((d)[3])               \
        : "r"((a)[0]), "r"((a)[1]), "r"((a)[2]), "r"((a)[3]),                  \
          "r"((b)[0]), "r"((b)[1]))

// ---------------------------------------------------------------------------
__device__ __forceinline__ int mapFlat(int r) {
    int win = r >> 6, t = r & 63;
    int b  = win >> 9;
    int wd = (win >> 6) & 7, wh = (win >> 3) & 7, ww = win & 7;
    int td = t >> 4, th = (t >> 2) & 3, tw = t & 3;
    int d0 = (wd * 4 + td + 2) & 31;
    int h0 = (wh * 4 + th + 2) & 31;
    int w0 = (ww * 4 + tw + 2) & 31;
    return ((b * 32 + d0) * 32 + h0) * 32 + w0;
}

// ---------------------------------------------------------------------------
__global__ void transpose_h(const float* __restrict__ in, __half* __restrict__ out,
                            int K, int N)
{
    __shared__ float t[32][33];
    int n0 = blockIdx.x * 32, k0 = blockIdx.y * 32;
    int x = threadIdx.x, y = threadIdx.y;
#pragma unroll
    for (int i = 0; i < 4; i++)
        t[y + i * 8][x] = in[(size_t)(k0 + y + i * 8) * N + n0 + x];
    __syncthreads();
#pragma unroll
    for (int i = 0; i < 4; i++)
        out[(size_t)(n0 + y + i * 8) * K + k0 + x] = __float2half_rn(t[x][y + i * 8]);
}

// ---------------------------------------------------------------------------
template <bool MAPPED>
__global__ void __launch_bounds__(256) ln_kernel(
    const float* __restrict__ in, const float* __restrict__ gam,
    const float* __restrict__ bet, __half* __restrict__ out)
{
    int warp = threadIdx.x >> 5, lane = threadIdx.x & 31;
    int r = blockIdx.x * 8 + warp;
    int src = MAPPED ? mapFlat(r) : r;

    const float4* ip = (const float4*)(in + (size_t)src * CDIM);
    float4 vals[4];
    float s = 0.f, sq = 0.f;
#pragma unroll
    for (int w = 0; w < 4; w++) {
        float4 v = ip[w * 32 + lane];
        vals[w] = v;
        s  += v.x + v.y + v.z + v.w;
        sq += v.x * v.x + v.y * v.y + v.z * v.z + v.w * v.w;
    }
#pragma unroll
    for (int o = 16; o > 0; o >>= 1) {
        s  += __shfl_xor_sync(0xffffffffu, s,  o);
        sq += __shfl_xor_sync(0xffffffffu, sq, o);
    }
    float m  = s * (1.0f / CDIM);
    float var = sq * (1.0f / CDIM) - m * m;
    float rs = rsqrtf(var + 1e-5f);

    __half2* op = (__half2*)(out + (size_t)r * CDIM);
    const float4* gp = (const float4*)gam;
    const float4* bp = (const float4*)bet;
#pragma unroll
    for (int w = 0; w < 4; w++) {
        int c4 = w * 32 + lane;
        float4 g = gp[c4], b = bp[c4], x = vals[w];
        op[c4 * 2]     = __floats2half2_rn((x.x - m) * rs * g.x + b.x,
                                           (x.y - m) * rs * g.y + b.y);
        op[c4 * 2 + 1] = __floats2half2_rn((x.z - m) * rs * g.z + b.z,
                                           (x.w - m) * rs * g.w + b.w);
    }
}

// ---------------------------------------------------------------------------
// fp16 GEMM: C[M,N] = A[M,K] @ Bt[N,K]^T  (block 128x256, BK=64, 3 stages,
// one barrier per iter, ldmatrix fragment loads).
// ---------------------------------------------------------------------------
#define BM 128
#define BN 256
#define BK 64
#define ASTR 72                   // halfs per smem row (16B-bank-distinct)
#define A_HALFS (BM * ASTR)       // 9216
#define B_HALFS (BN * ASTR)       // 18432
#define STAGES 3
#define GEMM_SMEM (STAGES * (A_HALFS + B_HALFS) * 2)

template <int EPI, typename OutT>
__global__ void __launch_bounds__(256, 1) tc_gemm(
    const __half* __restrict__ A, const __half* __restrict__ Bt,
    const float* __restrict__ bias, const float* __restrict__ resid,
    OutT* __restrict__ C, int M, int N, int K)
{
    extern __shared__ __half smh[];
    __half* Asm[STAGES];
    __half* Bsm[STAGES];
    uint32_t Au[STAGES], Bu[STAGES];
#pragma unroll
    for (int s = 0; s < STAGES; s++) {
        Asm[s] = smh + s * A_HALFS;
        Bsm[s] = smh + STAGES * A_HALFS + s * B_HALFS;
        Au[s] = smem_u32(Asm[s]);
        Bu[s] = smem_u32(Bsm[s]);
    }

    int tid = threadIdx.x;
    int wid = tid >> 5, lane = tid & 31;
    int wm = wid >> 2, wn = wid & 3;
    int lr = lane >> 2, lc = lane & 3;
    int m0 = blockIdx.y * BM, n0 = blockIdx.x * BN;

    // ldmatrix lane offsets (halfs)
    int a_lane = ((lane & 7) + ((lane >> 3) & 1) * 8) * ASTR + (lane >> 4) * 8
               + wm * 64 * ASTR;
    int b_lane = ((lane & 7) + (lane >> 4) * 8) * ASTR + ((lane >> 3) & 1) * 8
               + wn * 64 * ASTR;

    float acc[4][8][4];
#pragma unroll
    for (int i = 0; i < 4; i++)
#pragma unroll
        for (int j = 0; j < 8; j++)
#pragma unroll
            for (int q = 0; q < 4; q++) acc[i][j][q] = 0.f;

    const int NCH = K >> 6;

    auto issue = [&](int it) {
        int s = it % STAGES;
        const __half* Ab = A + (size_t)m0 * K + it * BK;
#pragma unroll
        for (int i = 0; i < 4; i++) {          // A: 128 rows x 8 chunks
            int idx = i * 256 + tid;
            int row = idx >> 3, c = idx & 7;
            cp16(Asm[s] + row * ASTR + c * 8, Ab + (size_t)row * K + c * 8);
        }
        const __half* Bb = Bt + (size_t)n0 * K + it * BK;
#pragma unroll
        for (int i = 0; i < 8; i++) {          // B: 256 rows x 8 chunks
            int idx = i * 256 + tid;
            int row = idx >> 3, c = idx & 7;
            cp16(Bsm[s] + row * ASTR + c * 8, Bb + (size_t)row * K + c * 8);
        }
        CP_COMMIT();
    };

    issue(0);
    issue(1);

    for (int it = 0; it < NCH; it++) {
        if (it + 1 < NCH) cp_wait<1>();
        else              cp_wait<0>();
        __syncthreads();
        if (it + 2 < NCH) issue(it + 2);

        int s = it % STAGES;
#pragma unroll
        for (int ks = 0; ks < 4; ks++) {
            uint32_t a[4][4];
#pragma unroll
            for (int mi = 0; mi < 4; mi++)
                LDSM4(a[mi][0], a[mi][1], a[mi][2], a[mi][3],
                      Au[s] + 2 * (a_lane + mi * 16 * ASTR + ks * 16));
            uint32_t b[8][2];
#pragma unroll
            for (int np = 0; np < 4; np++)
                LDSM4(b[2 * np][0], b[2 * np][1], b[2 * np + 1][0], b[2 * np + 1][1],
                      Bu[s] + 2 * (b_lane + np * 16 * ASTR + ks * 16));
#pragma unroll
            for (int mi = 0; mi < 4; mi++)
#pragma unroll
                for (int ni = 0; ni < 8; ni++)
                    MMA_F16(acc[mi][ni], a[mi], b[ni]);
        }
    }

    // Epilogue
#pragma unroll
    for (int mi = 0; mi < 4; mi++) {
        int r0 = m0 + wm * 64 + mi * 16 + lr;
        size_t rb0, rb1;
        if (EPI == 2) { rb0 = (size_t)mapFlat(r0) * CDIM;
                        rb1 = (size_t)mapFlat(r0 + 8) * CDIM; }
        else          { rb0 = (size_t)r0 * N; rb1 = rb0 + (size_t)8 * N; }
#pragma unroll
        for (int ni = 0; ni < 8; ni++) {
            int c = n0 + wn * 64 + ni * 8 + lc * 2;
            float2 bs = *(const float2*)(bias + c);
            float v0 = acc[mi][ni][0] + bs.x, v1 = acc[mi][ni][1] + bs.y;
            float v2 = acc[mi][ni][2] + bs.x, v3 = acc[mi][ni][3] + bs.y;
            if (EPI == 1) {
                v0 = 0.5f * v0 * (1.0f + erff(v0 * 0.70710678118654752f));
                v1 = 0.5f * v1 * (1.0f + erff(v1 * 0.70710678118654752f));
                v2 = 0.5f * v2 * (1.0f + erff(v2 * 0.70710678118654752f));
                v3 = 0.5f * v3 * (1.0f + erff(v3 * 0.70710678118654752f));
            }
            if (EPI == 2 || EPI == 3) {
                float2 r0v = *(const float2*)(resid + rb0 + c);
                float2 r1v = *(const float2*)(resid + rb1 + c);
                v0 += r0v.x; v1 += r0v.y; v2 += r1v.x; v3 += r1v.y;
                float* Cf = (float*)C;
                *(float2*)(Cf + rb0 + c) = make_float2(v0, v1);
                *(float2*)(Cf + rb1 + c) = make_float2(v2, v3);
            } else {
                __half* Ch = (__half*)C;
                *(__half2*)(Ch + rb0 + c) = __floats2half2_rn(v0, v1);
                *(__half2*)(Ch + rb1 + c) = __floats2half2_rn(v2, v3);
            }
        }
    }
}

// ---------------------------------------------------------------------------
// Tensor-core windowed attention. Block = (window, 4 heads), 8 warps.
// Warp pair per head; warp owns 32 query rows. S=QK^T via mma (K is natural
// [n][k] B operand); in-register softmax; P->half into Q buffer; O=PV with
// ldmatrix.trans on V.
// ---------------------------------------------------------------------------
#define HP 72
#define ATTN_SMEM (4 * 3 * 64 * HP * 2)

__global__ void __launch_bounds__(256) attn_kernel(
    const __half* __restrict__ qkv, __half* __restrict__ out)
{
    extern __shared__ __half sh[];
    int tid = threadIdx.x, wid = tid >> 5, lane = tid & 31;
    int lr = lane >> 2, lc = lane & 3;
    int win = blockIdx.x >> 1;
    int head = (blockIdx.x & 1) * 4 + (wid >> 1);
    int mh = wid & 1;                          // row half: 0 or 1

    __half* Qs = sh + (wid >> 1) * 3 * 64 * HP;
    __half* Ks = Qs + 64 * HP;
    __half* Vs = Ks + 64 * HP;
    const __half* base = qkv + (size_t)win * 64 * QKVDIM + head * 64;

    // load own 32 rows of Q, K, V (each row: 8 x 16B chunks)
#pragma unroll
    for (int i = 0; i < 24; i++) {
        int idx = i * 32 + lane;               // 0..767
        int tens = idx >> 8;                   // 0:Q 1:K 2:V (256 chunks each)
        int rem = idx & 255;
        int t = mh * 32 + (rem >> 3), c = rem & 7;
        const uint4* gp = (const uint4*)(base + (size_t)t * QKVDIM + tens * 512 + c * 8);
        __half* dst = (tens == 0 ? Qs : tens == 1 ? Ks : Vs) + t * HP + c * 8;
        *(uint4*)dst = *gp;
    }
    __syncthreads();

    uint32_t qb = smem_u32(Qs), kb = smem_u32(Ks), vb = smem_u32(Vs);
    int a_lane = ((lane & 7) + ((lane >> 3) & 1) * 8) * HP + (lane >> 4) * 8;
    int b_lane = ((lane & 7) + (lane >> 4) * 8) * HP + ((lane >> 3) & 1) * 8;

    // S = Q @ K^T
    float sacc[2][8][4];
#pragma unroll
    for (int i = 0; i < 2; i++)
#pragma unroll
        for (int j = 0; j < 8; j++)
#pragma unroll
            for (int q = 0; q < 4; q++) sacc[i][j][q] = 0.f;

#pragma unroll
    for (int ks = 0; ks < 4; ks++) {
        uint32_t a[2][4];
#pragma unroll
        for (int mi = 0; mi < 2; mi++)
            LDSM4(a[mi][0], a[mi][1], a[mi][2], a[mi][3],
                  qb + 2 * (mh * 32 * HP + mi * 16 * HP + ks * 16 + a_lane));
        uint32_t b[8][2];
#pragma unroll
        for (int np = 0; np < 4; np++)
            LDSM4(b[2 * np][0], b[2 * np][1], b[2 * np + 1][0], b[2 * np + 1][1],
                  kb + 2 * (np * 16 * HP + ks * 16 + b_lane));
#pragma unroll
        for (int mi = 0; mi < 2; mi++)
#pragma unroll
            for (int ni = 0; ni < 8; ni++)
                MMA_F16(sacc[mi][ni], a[mi], b[ni]);
    }

    // softmax (scale 1/8) + pack P into Q buffer (own rows only)
#pragma unroll
    for (int mi = 0; mi < 2; mi++) {
        float mx0 = -1e30f, mx1 = -1e30f;
#pragma unroll
        for (int ni = 0; ni < 8; ni++) {
#pragma unroll
            for (int q = 0; q < 4; q++) sacc[mi][ni][q] *= 0.125f;
            mx0 = fmaxf(mx0, fmaxf(sacc[mi][ni][0], sacc[mi][ni][1]));
            mx1 = fmaxf(mx1, fmaxf(sacc[mi][ni][2], sacc[mi][ni][3]));
        }
        mx0 = fmaxf(mx0, __shfl_xor_sync(0xffffffffu, mx0, 1));
        mx0 = fmaxf(mx0, __shfl_xor_sync(0xffffffffu, mx0, 2));
        mx1 = fmaxf(mx1, __shfl_xor_sync(0xffffffffu, mx1, 1));
        mx1 = fmaxf(mx1, __shfl_xor_sync(0xffffffffu, mx1, 2));
        float s0 = 0.f, s1 = 0.f;
#pragma unroll
        for (int ni = 0; ni < 8; ni++) {
            sacc[mi][ni][0] = __expf(sacc[mi][ni][0] - mx0);
            sacc[mi][ni][1] = __expf(sacc[mi][ni][1] - mx0);
            sacc[mi][ni][2] = __expf(sacc[mi][ni][2] - mx1);
            sacc[mi][ni][3] = __expf(sacc[mi][ni][3] - mx1);
            s0 += sacc[mi][ni][0] + sacc[mi][ni][1];
            s1 += sacc[mi][ni][2] + sacc[mi][ni][3];
        }
        s0 += __shfl_xor_sync(0xffffffffu, s0, 1);
        s0 += __shfl_xor_sync(0xffffffffu, s0, 2);
        s1 += __shfl_xor_sync(0xffffffffu, s1, 1);
        s1 += __shfl_xor_sync(0xffffffffu, s1, 2);
        float i0 = 1.0f / s0, i1 = 1.0f / s1;
        int row0 = mh * 32 + mi * 16 + lr;
#pragma unroll
        for (int ni = 0; ni < 8; ni++) {
            int cc = ni * 8 + lc * 2;
            *(__half2*)(Qs + row0 * HP + cc) =
                __floats2half2_rn(sacc[mi][ni][0] * i0, sacc[mi][ni][1] * i0);
            *(__half2*)(Qs + (row0 + 8) * HP + cc) =
                __floats2half2_rn(sacc[mi][ni][2] * i1, sacc[mi][ni][3] * i1);
        }
    }
    __syncwarp();

    // O = P @ V  (V via ldmatrix.trans: B[n=d][k=t])
    float oacc[2][8][4];
#pragma unroll
    for (int i = 0; i < 2; i++)
#pragma unroll
        for (int j = 0; j < 8; j++)
#pragma unroll
            for (int q = 0; q < 4; q++) oacc[i][j][q] = 0.f;

#pragma unroll
    for (int ks = 0; ks < 4; ks++) {
        uint32_t a[2][4];
#pragma unroll
        for (int mi = 0; mi < 2; mi++)
            LDSM4(a[mi][0], a[mi][1], a[mi][2], a[mi][3],
                  qb + 2 * (mh * 32 * HP + mi * 16 * HP + ks * 16 + a_lane));
        uint32_t b[8][2];
#pragma unroll
        for (int np = 0; np < 4; np++)
            LDSM4T(b[2 * np][0], b[2 * np][1], b[2 * np + 1][0], b[2 * np + 1][1],
                   vb + 2 * (ks * 16 * HP + np * 16 + a_lane));
#pragma unroll
        for (int mi = 0; mi < 2; mi++)
#pragma unroll
            for (int ni = 0; ni < 8; ni++)
                MMA_F16(oacc[mi][ni], a[mi], b[ni]);
    }

    // store O
#pragma unroll
    for (int mi = 0; mi < 2; mi++) {
        int row0 = win * 64 + mh * 32 + mi * 16 + lr;
#pragma unroll
        for (int ni = 0; ni < 8; ni++) {
            int col = head * 64 + ni * 8 + lc * 2;
            *(__half2*)(out + (size_t)row0 * CDIM + col) =
                __floats2half2_rn(oacc[mi][ni][0], oacc[mi][ni][1]);
            *(__half2*)(out + (size_t)(row0 + 8) * CDIM + col) =
                __floats2half2_rn(oacc[mi][ni][2], oacc[mi][ni][3]);
        }
    }
}

// ---------------------------------------------------------------------------
extern "C" void kernel_launch(void* const* d_in, const int* in_sizes, int n_in,
                              void* d_out, int out_size)
{
    const float* x      = (const float*)d_in[0];
    const float* ln1_g  = (const float*)d_in[1];
    const float* ln1_b  = (const float*)d_in[2];
    const float* qkv_w  = (const float*)d_in[3];
    const float* qkv_b  = (const float*)d_in[4];
    const float* proj_w = (const float*)d_in[5];
    const float* proj_b = (const float*)d_in[6];
    const float* ln2_g  = (const float*)d_in[7];
    const float* ln2_b  = (const float*)d_in[8];
    const float* ffn_w1 = (const float*)d_in[9];
    const float* ffn_b1 = (const float*)d_in[10];
    const float* ffn_w2 = (const float*)d_in[11];
    const float* ffn_b2 = (const float*)d_in[12];
    float* out = (float*)d_out;

    __half *p_h, *p_qkv, *p_attn, *p_h2, *p_hid;
    __half *p_qkvw, *p_projw, *p_w1, *p_w2;
    float *p_xo;
    cudaGetSymbolAddress((void**)&p_h,    g_h);
    cudaGetSymbolAddress((void**)&p_qkv,  g_qkv);
    cudaGetSymbolAddress((void**)&p_attn, g_attn);
    cudaGetSymbolAddress((void**)&p_xo,   g_xo);
    cudaGetSymbolAddress((void**)&p_h2,   g_h2);
    cudaGetSymbolAddress((void**)&p_hid,  g_hid);
    cudaGetSymbolAddress((void**)&p_qkvw, g_qkvw);
    cudaGetSymbolAddress((void**)&p_projw,g_projw);
    cudaGetSymbolAddress((void**)&p_w1,   g_w1);
    cudaGetSymbolAddress((void**)&p_w2,   g_w2);

    cudaFuncSetAttribute(attn_kernel,
                         cudaFuncAttributeMaxDynamicSharedMemorySize, ATTN_SMEM);
    cudaFuncSetAttribute((tc_gemm<0, __half>), cudaFuncAttributeMaxDynamicSharedMemorySize, GEMM_SMEM);
    cudaFuncSetAttribute((tc_gemm<1, __half>), cudaFuncAttributeMaxDynamicSharedMemorySize, GEMM_SMEM);
    cudaFuncSetAttribute((tc_gemm<2, float>),  cudaFuncAttributeMaxDynamicSharedMemorySize, GEMM_SMEM);
    cudaFuncSetAttribute((tc_gemm<3, float>),  cudaFuncAttributeMaxDynamicSharedMemorySize, GEMM_SMEM);

    // 0. weight transpose + fp16 convert
    transpose_h<<<dim3(QKVDIM / 32, CDIM / 32),   dim3(32, 8)>>>(qkv_w,  p_qkvw,  CDIM,   QKVDIM);
    transpose_h<<<dim3(CDIM / 32,   CDIM / 32),   dim3(32, 8)>>>(proj_w, p_projw, CDIM,   CDIM);
    transpose_h<<<dim3(HIDDIM / 32, CDIM / 32),   dim3(32, 8)>>>(ffn_w1, p_w1,    CDIM,   HIDDIM);
    transpose_h<<<dim3(CDIM / 32,   HIDDIM / 32), dim3(32, 8)>>>(ffn_w2, p_w2,    HIDDIM, CDIM);

    // 1. shift + window partition + LN1
    ln_kernel<true><<<NROWS / 8, 256>>>(x, ln1_g, ln1_b, p_h);

    // 2. QKV GEMM
    tc_gemm<0, __half><<<dim3(QKVDIM / BN, NROWS / BM), 256, GEMM_SMEM>>>(
        p_h, p_qkvw, qkv_b, nullptr, p_qkv, NROWS, QKVDIM, CDIM);

    // 3. windowed attention (tensor cores)
    attn_kernel<<<1024 * 2, 256, ATTN_SMEM>>>(p_qkv, p_attn);

    // 4. proj GEMM + residual + window-reverse scatter
    tc_gemm<2, float><<<dim3(CDIM / BN, NROWS / BM), 256, GEMM_SMEM>>>(
        p_attn, p_projw, proj_b, x, p_xo, NROWS, CDIM, CDIM);

    // 5. LN2
    ln_kernel<false><<<NROWS / 8, 256>>>(p_xo, ln2_g, ln2_b, p_h2);

    // 6. FFN1 GEMM + GELU
    tc_gemm<1, __half><<<dim3(HIDDIM / BN, NROWS / BM), 256, GEMM_SMEM>>>(
        p_h2, p_w1, ffn_b1, nullptr, p_hid, NROWS, HIDDIM, CDIM);

    // 7. FFN2 GEMM + residual -> out
    tc_gemm<3, float><<<dim3(CDIM / BN, NROWS / BM), 256, GEMM_SMEM>>>(
        p_hid, p_w2, ffn_b2, p_xo, out, NROWS, CDIM, HIDDIM);
}

// round 11
// speedup vs baseline: 5.7667x; 1.0271x over previous
#include <cuda_runtime.h>
#include <cuda_fp16.h>
#include <math.h>
#include <stdint.h>

// ---------------------------------------------------------------------------
// Windowed 3D attention block — fp16 mma.sync GEMMs, BN=128 tiles at
// 2 CTAs/SM (occupancy play), ldmatrix + BK=64 3-stage single-barrier
// pipeline; tensor-core windowed attention.
// ---------------------------------------------------------------------------

#define NROWS   65536
#define CDIM    512
#define QKVDIM  1536
#define HIDDIM  2048

__device__ __half g_h   [ (size_t)NROWS * CDIM  ];
__device__ __half g_qkv [ (size_t)NROWS * QKVDIM];
__device__ __half g_attn[ (size_t)NROWS * CDIM  ];
__device__ float  g_xo  [ (size_t)NROWS * CDIM  ];
__device__ __half g_h2  [ (size_t)NROWS * CDIM  ];
__device__ __half g_hid [ (size_t)NROWS * HIDDIM];
__device__ __half g_qkvw [(size_t)QKVDIM * CDIM];
__device__ __half g_projw[(size_t)CDIM * CDIM  ];
__device__ __half g_w1   [(size_t)HIDDIM * CDIM];
__device__ __half g_w2   [(size_t)CDIM * HIDDIM];

// ---------------------------------------------------------------------------
__device__ __forceinline__ uint32_t smem_u32(const void* p) {
    uint32_t a;
    asm("{ .reg .u64 t; cvta.to.shared.u64 t, %1; cvt.u32.u64 %0, t; }"
        : "=r"(a) : "l"(p));
    return a;
}

__device__ __forceinline__ void cp16(void* dst, const void* src) {
    asm volatile("cp.async.cg.shared.global [%0], [%1], 16;"
                 :: "r"(smem_u32(dst)), "l"(src));
}
#define CP_COMMIT() asm volatile("cp.async.commit_group;" ::: "memory")
template <int N>
__device__ __forceinline__ void cp_wait() {
    asm volatile("cp.async.wait_group %0;" :: "n"(N) : "memory");
}

#define LDSM4(r0, r1, r2, r3, addr)                                            \
    asm volatile("ldmatrix.sync.aligned.m8n8.x4.shared.b16 {%0,%1,%2,%3}, [%4];" \
        : "=r"(r0), "=r"(r1), "=r"(r2), "=r"(r3) : "r"(addr))

#define LDSM4T(r0, r1, r2, r3, addr)                                           \
    asm volatile("ldmatrix.sync.aligned.m8n8.x4.trans.shared.b16 {%0,%1,%2,%3}, [%4];" \
        : "=r"(r0), "=r"(r1), "=r"(r2), "=r"(r3) : "r"(addr))

#define MMA_F16(d, a, b)                                                       \
    asm volatile(                                                              \
        "mma.sync.aligned.m16n8k16.row.col.f32.f16.f16.f32 "                   \
        "{%0,%1,%2,%3}, {%4,%5,%6,%7}, {%8,%9}, {%0,%1,%2,%3};"                \
        : "+f"((d)[0]), "+f"((d)[1]), "+f"((d)[2]), "+f"((d)[3])               \
        : "r"((a)[0]), "r"((a)[1]), "r"((a)[2]), "r"((a)[3]),                  \
          "r"((b)[0]), "r"((b)[1]))

// ---------------------------------------------------------------------------
__device__ __forceinline__ int mapFlat(int r) {
    int win = r >> 6, t = r & 63;
    int b  = win >> 9;
    int wd = (win >> 6) & 7, wh = (win >> 3) & 7, ww = win & 7;
    int td = t >> 4, th = (t >> 2) & 3, tw = t & 3;
    int d0 = (wd * 4 + td + 2) & 31;
    int h0 = (wh * 4 + th + 2) & 31;
    int w0 = (ww * 4 + tw + 2) & 31;
    return ((b * 32 + d0) * 32 + h0) * 32 + w0;
}

// ---------------------------------------------------------------------------
// All 4 weight transposes in ONE launch. float [K][N] -> half [N][K].
// ---------------------------------------------------------------------------
__global__ void transpose_all(
    const float* __restrict__ qkvw, const float* __restrict__ projw,
    const float* __restrict__ w1,   const float* __restrict__ w2,
    __half* __restrict__ o_qkvw, __half* __restrict__ o_projw,
    __half* __restrict__ o_w1,   __half* __restrict__ o_w2)
{
    __shared__ float t[32][33];
    int id = blockIdx.x;
    const float* in; __half* out; int K, N, nblk;
    if (id < 768)       { in = qkvw;  out = o_qkvw;  K = 512;  N = 1536; nblk = 48; }
    else if (id < 1024) { in = projw; out = o_projw; K = 512;  N = 512;  nblk = 16; id -= 768; }
    else if (id < 2048) { in = w1;    out = o_w1;    K = 512;  N = 2048; nblk = 64; id -= 1024; }
    else                { in = w2;    out = o_w2;    K = 2048; N = 512;  nblk = 16; id -= 2048; }
    int n0 = (id % nblk) * 32, k0 = (id / nblk) * 32;
    int x = threadIdx.x, y = threadIdx.y;
#pragma unroll
    for (int i = 0; i < 4; i++)
        t[y + i * 8][x] = in[(size_t)(k0 + y + i * 8) * N + n0 + x];
    __syncthreads();
#pragma unroll
    for (int i = 0; i < 4; i++)
        out[(size_t)(n0 + y + i * 8) * K + k0 + x] = __float2half_rn(t[x][y + i * 8]);
}

// ---------------------------------------------------------------------------
template <bool MAPPED>
__global__ void __launch_bounds__(256) ln_kernel(
    const float* __restrict__ in, const float* __restrict__ gam,
    const float* __restrict__ bet, __half* __restrict__ out)
{
    int warp = threadIdx.x >> 5, lane = threadIdx.x & 31;
    int r = blockIdx.x * 8 + warp;
    int src = MAPPED ? mapFlat(r) : r;

    const float4* ip = (const float4*)(in + (size_t)src * CDIM);
    float4 vals[4];
    float s = 0.f, sq = 0.f;
#pragma unroll
    for (int w = 0; w < 4; w++) {
        float4 v = ip[w * 32 + lane];
        vals[w] = v;
        s  += v.x + v.y + v.z + v.w;
        sq += v.x * v.x + v.y * v.y + v.z * v.z + v.w * v.w;
    }
#pragma unroll
    for (int o = 16; o > 0; o >>= 1) {
        s  += __shfl_xor_sync(0xffffffffu, s,  o);
        sq += __shfl_xor_sync(0xffffffffu, sq, o);
    }
    float m  = s * (1.0f / CDIM);
    float var = sq * (1.0f / CDIM) - m * m;
    float rs = rsqrtf(var + 1e-5f);

    __half2* op = (__half2*)(out + (size_t)r * CDIM);
    const float4* gp = (const float4*)gam;
    const float4* bp = (const float4*)bet;
#pragma unroll
    for (int w = 0; w < 4; w++) {
        int c4 = w * 32 + lane;
        float4 g = gp[c4], b = bp[c4], x = vals[w];
        op[c4 * 2]     = __floats2half2_rn((x.x - m) * rs * g.x + b.x,
                                           (x.y - m) * rs * g.y + b.y);
        op[c4 * 2 + 1] = __floats2half2_rn((x.z - m) * rs * g.z + b.z,
                                           (x.w - m) * rs * g.w + b.w);
    }
}

// ---------------------------------------------------------------------------
// fp16 GEMM: C[M,N] = A[M,K] @ Bt[N,K]^T  (block 128x128, BK=64, 3 stages,
// 2 CTAs/SM). 8 warps in 4x2 grid; warp tile 32x64 (mi=2, ni=8).
// ---------------------------------------------------------------------------
#define BM 128
#define BN 128
#define BK 64
#define ASTR 72
#define A_HALFS (BM * ASTR)       // 9216
#define B_HALFS (BN * ASTR)       // 9216
#define STAGES 3
#define GEMM_SMEM (STAGES * (A_HALFS + B_HALFS) * 2)   // 110592 B

template <int EPI, typename OutT>
__global__ void __launch_bounds__(256, 2) tc_gemm(
    const __half* __restrict__ A, const __half* __restrict__ Bt,
    const float* __restrict__ bias, const float* __restrict__ resid,
    OutT* __restrict__ C, int M, int N, int K)
{
    extern __shared__ __half smh[];
    __half* Asm[STAGES];
    __half* Bsm[STAGES];
    uint32_t Au[STAGES], Bu[STAGES];
#pragma unroll
    for (int s = 0; s < STAGES; s++) {
        Asm[s] = smh + s * A_HALFS;
        Bsm[s] = smh + STAGES * A_HALFS + s * B_HALFS;
        Au[s] = smem_u32(Asm[s]);
        Bu[s] = smem_u32(Bsm[s]);
    }

    int tid = threadIdx.x;
    int wid = tid >> 5, lane = tid & 31;
    int wm = wid >> 1, wn = wid & 1;          // 4 x 2 warp grid
    int lr = lane >> 2, lc = lane & 3;
    int m0 = blockIdx.y * BM, n0 = blockIdx.x * BN;

    int a_lane = ((lane & 7) + ((lane >> 3) & 1) * 8) * ASTR + (lane >> 4) * 8
               + wm * 32 * ASTR;
    int b_lane = ((lane & 7) + (lane >> 4) * 8) * ASTR + ((lane >> 3) & 1) * 8
               + wn * 64 * ASTR;

    float acc[2][8][4];
#pragma unroll
    for (int i = 0; i < 2; i++)
#pragma unroll
        for (int j = 0; j < 8; j++)
#pragma unroll
            for (int q = 0; q < 4; q++) acc[i][j][q] = 0.f;

    const int NCH = K >> 6;

    auto issue = [&](int it) {
        int s = it % STAGES;
        const __half* Ab = A + (size_t)m0 * K + it * BK;
#pragma unroll
        for (int i = 0; i < 4; i++) {          // A: 128 rows x 8 chunks
            int idx = i * 256 + tid;
            int row = idx >> 3, c = idx & 7;
            cp16(Asm[s] + row * ASTR + c * 8, Ab + (size_t)row * K + c * 8);
        }
        const __half* Bb = Bt + (size_t)n0 * K + it * BK;
#pragma unroll
        for (int i = 0; i < 4; i++) {          // B: 128 rows x 8 chunks
            int idx = i * 256 + tid;
            int row = idx >> 3, c = idx & 7;
            cp16(Bsm[s] + row * ASTR + c * 8, Bb + (size_t)row * K + c * 8);
        }
        CP_COMMIT();
    };

    issue(0);
    issue(1);

    for (int it = 0; it < NCH; it++) {
        if (it + 1 < NCH) cp_wait<1>();
        else              cp_wait<0>();
        __syncthreads();
        if (it + 2 < NCH) issue(it + 2);

        int s = it % STAGES;
#pragma unroll
        for (int ks = 0; ks < 4; ks++) {
            uint32_t a[2][4];
#pragma unroll
            for (int mi = 0; mi < 2; mi++)
                LDSM4(a[mi][0], a[mi][1], a[mi][2], a[mi][3],
                      Au[s] + 2 * (a_lane + mi * 16 * ASTR + ks * 16));
            uint32_t b[8][2];
#pragma unroll
            for (int np = 0; np < 4; np++)
                LDSM4(b[2 * np][0], b[2 * np][1], b[2 * np + 1][0], b[2 * np + 1][1],
                      Bu[s] + 2 * (b_lane + np * 16 * ASTR + ks * 16));
#pragma unroll
            for (int mi = 0; mi < 2; mi++)
#pragma unroll
                for (int ni = 0; ni < 8; ni++)
                    MMA_F16(acc[mi][ni], a[mi], b[ni]);
        }
    }

    // Epilogue
#pragma unroll
    for (int mi = 0; mi < 2; mi++) {
        int r0 = m0 + wm * 32 + mi * 16 + lr;
        size_t rb0, rb1;
        if (EPI == 2) { rb0 = (size_t)mapFlat(r0) * CDIM;
                        rb1 = (size_t)mapFlat(r0 + 8) * CDIM; }
        else          { rb0 = (size_t)r0 * N; rb1 = rb0 + (size_t)8 * N; }
#pragma unroll
        for (int ni = 0; ni < 8; ni++) {
            int c = n0 + wn * 64 + ni * 8 + lc * 2;
            float2 bs = *(const float2*)(bias + c);
            float v0 = acc[mi][ni][0] + bs.x, v1 = acc[mi][ni][1] + bs.y;
            float v2 = acc[mi][ni][2] + bs.x, v3 = acc[mi][ni][3] + bs.y;
            if (EPI == 1) {
                v0 = 0.5f * v0 * (1.0f + erff(v0 * 0.70710678118654752f));
                v1 = 0.5f * v1 * (1.0f + erff(v1 * 0.70710678118654752f));
                v2 = 0.5f * v2 * (1.0f + erff(v2 * 0.70710678118654752f));
                v3 = 0.5f * v3 * (1.0f + erff(v3 * 0.70710678118654752f));
            }
            if (EPI == 2 || EPI == 3) {
                float2 r0v = *(const float2*)(resid + rb0 + c);
                float2 r1v = *(const float2*)(resid + rb1 + c);
                v0 += r0v.x; v1 += r0v.y; v2 += r1v.x; v3 += r1v.y;
                float* Cf = (float*)C;
                *(float2*)(Cf + rb0 + c) = make_float2(v0, v1);
                *(float2*)(Cf + rb1 + c) = make_float2(v2, v3);
            } else {
                __half* Ch = (__half*)C;
                *(__half2*)(Ch + rb0 + c) = __floats2half2_rn(v0, v1);
                *(__half2*)(Ch + rb1 + c) = __floats2half2_rn(v2, v3);
            }
        }
    }
}

// ---------------------------------------------------------------------------
// Tensor-core windowed attention. Block = (window, 4 heads), 8 warps.
// ---------------------------------------------------------------------------
#define HP 72
#define ATTN_SMEM (4 * 3 * 64 * HP * 2)

__global__ void __launch_bounds__(256) attn_kernel(
    const __half* __restrict__ qkv, __half* __restrict__ out)
{
    extern __shared__ __half sh[];
    int tid = threadIdx.x, wid = tid >> 5, lane = tid & 31;
    int lr = lane >> 2, lc = lane & 3;
    int win = blockIdx.x >> 1;
    int head = (blockIdx.x & 1) * 4 + (wid >> 1);
    int mh = wid & 1;

    __half* Qs = sh + (wid >> 1) * 3 * 64 * HP;
    __half* Ks = Qs + 64 * HP;
    __half* Vs = Ks + 64 * HP;
    const __half* base = qkv + (size_t)win * 64 * QKVDIM + head * 64;

#pragma unroll
    for (int i = 0; i < 24; i++) {
        int idx = i * 32 + lane;
        int tens = idx >> 8;
        int rem = idx & 255;
        int t = mh * 32 + (rem >> 3), c = rem & 7;
        const uint4* gp = (const uint4*)(base + (size_t)t * QKVDIM + tens * 512 + c * 8);
        __half* dst = (tens == 0 ? Qs : tens == 1 ? Ks : Vs) + t * HP + c * 8;
        *(uint4*)dst = *gp;
    }
    __syncthreads();

    uint32_t qb = smem_u32(Qs), kb = smem_u32(Ks), vb = smem_u32(Vs);
    int a_lane = ((lane & 7) + ((lane >> 3) & 1) * 8) * HP + (lane >> 4) * 8;
    int b_lane = ((lane & 7) + (lane >> 4) * 8) * HP + ((lane >> 3) & 1) * 8;

    float sacc[2][8][4];
#pragma unroll
    for (int i = 0; i < 2; i++)
#pragma unroll
        for (int j = 0; j < 8; j++)
#pragma unroll
            for (int q = 0; q < 4; q++) sacc[i][j][q] = 0.f;

#pragma unroll
    for (int ks = 0; ks < 4; ks++) {
        uint32_t a[2][4];
#pragma unroll
        for (int mi = 0; mi < 2; mi++)
            LDSM4(a[mi][0], a[mi][1], a[mi][2], a[mi][3],
                  qb + 2 * (mh * 32 * HP + mi * 16 * HP + ks * 16 + a_lane));
        uint32_t b[8][2];
#pragma unroll
        for (int np = 0; np < 4; np++)
            LDSM4(b[2 * np][0], b[2 * np][1], b[2 * np + 1][0], b[2 * np + 1][1],
                  kb + 2 * (np * 16 * HP + ks * 16 + b_lane));
#pragma unroll
        for (int mi = 0; mi < 2; mi++)
#pragma unroll
            for (int ni = 0; ni < 8; ni++)
                MMA_F16(sacc[mi][ni], a[mi], b[ni]);
    }

#pragma unroll
    for (int mi = 0; mi < 2; mi++) {
        float mx0 = -1e30f, mx1 = -1e30f;
#pragma unroll
        for (int ni = 0; ni < 8; ni++) {
#pragma unroll
            for (int q = 0; q < 4; q++) sacc[mi][ni][q] *= 0.125f;
            mx0 = fmaxf(mx0, fmaxf(sacc[mi][ni][0], sacc[mi][ni][1]));
            mx1 = fmaxf(mx1, fmaxf(sacc[mi][ni][2], sacc[mi][ni][3]));
        }
        mx0 = fmaxf(mx0, __shfl_xor_sync(0xffffffffu, mx0, 1));
        mx0 = fmaxf(mx0, __shfl_xor_sync(0xffffffffu, mx0, 2));
        mx1 = fmaxf(mx1, __shfl_xor_sync(0xffffffffu, mx1, 1));
        mx1 = fmaxf(mx1, __shfl_xor_sync(0xffffffffu, mx1, 2));
        float s0 = 0.f, s1 = 0.f;
#pragma unroll
        for (int ni = 0; ni < 8; ni++) {
            sacc[mi][ni][0] = __expf(sacc[mi][ni][0] - mx0);
            sacc[mi][ni][1] = __expf(sacc[mi][ni][1] - mx0);
            sacc[mi][ni][2] = __expf(sacc[mi][ni][2] - mx1);
            sacc[mi][ni][3] = __expf(sacc[mi][ni][3] - mx1);
            s0 += sacc[mi][ni][0] + sacc[mi][ni][1];
            s1 += sacc[mi][ni][2] + sacc[mi][ni][3];
        }
        s0 += __shfl_xor_sync(0xffffffffu, s0, 1);
        s0 += __shfl_xor_sync(0xffffffffu, s0, 2);
        s1 += __shfl_xor_sync(0xffffffffu, s1, 1);
        s1 += __shfl_xor_sync(0xffffffffu, s1, 2);
        float i0 = 1.0f / s0, i1 = 1.0f / s1;
        int row0 = mh * 32 + mi * 16 + lr;
#pragma unroll
        for (int ni = 0; ni < 8; ni++) {
            int cc = ni * 8 + lc * 2;
            *(__half2*)(Qs + row0 * HP + cc) =
                __floats2half2_rn(sacc[mi][ni][0] * i0, sacc[mi][ni][1] * i0);
            *(__half2*)(Qs + (row0 + 8) * HP + cc) =
                __floats2half2_rn(sacc[mi][ni][2] * i1, sacc[mi][ni][3] * i1);
        }
    }
    __syncwarp();

    float oacc[2][8][4];
#pragma unroll
    for (int i = 0; i < 2; i++)
#pragma unroll
        for (int j = 0; j < 8; j++)
#pragma unroll
            for (int q = 0; q < 4; q++) oacc[i][j][q] = 0.f;

#pragma unroll
    for (int ks = 0; ks < 4; ks++) {
        uint32_t a[2][4];
#pragma unroll
        for (int mi = 0; mi < 2; mi++)
            LDSM4(a[mi][0], a[mi][1], a[mi][2], a[mi][3],
                  qb + 2 * (mh * 32 * HP + mi * 16 * HP + ks * 16 + a_lane));
        uint32_t b[8][2];
#pragma unroll
        for (int np = 0; np < 4; np++)
            LDSM4T(b[2 * np][0], b[2 * np][1], b[2 * np + 1][0], b[2 * np + 1][1],
                   vb + 2 * (ks * 16 * HP + np * 16 + a_lane));
#pragma unroll
        for (int mi = 0; mi < 2; mi++)
#pragma unroll
            for (int ni = 0; ni < 8; ni++)
                MMA_F16(oacc[mi][ni], a[mi], b[ni]);
    }

#pragma unroll
    for (int mi = 0; mi < 2; mi++) {
        int row0 = win * 64 + mh * 32 + mi * 16 + lr;
#pragma unroll
        for (int ni = 0; ni < 8; ni++) {
            int col = head * 64 + ni * 8 + lc * 2;
            *(__half2*)(out + (size_t)row0 * CDIM + col) =
                __floats2half2_rn(oacc[mi][ni][0], oacc[mi][ni][1]);
            *(__half2*)(out + (size_t)(row0 + 8) * CDIM + col) =
                __floats2half2_rn(oacc[mi][ni][2], oacc[mi][ni][3]);
        }
    }
}

// ---------------------------------------------------------------------------
extern "C" void kernel_launch(void* const* d_in, const int* in_sizes, int n_in,
                              void* d_out, int out_size)
{
    const float* x      = (const float*)d_in[0];
    const float* ln1_g  = (const float*)d_in[1];
    const float* ln1_b  = (const float*)d_in[2];
    const float* qkv_w  = (const float*)d_in[3];
    const float* qkv_b  = (const float*)d_in[4];
    const float* proj_w = (const float*)d_in[5];
    const float* proj_b = (const float*)d_in[6];
    const float* ln2_g  = (const float*)d_in[7];
    const float* ln2_b  = (const float*)d_in[8];
    const float* ffn_w1 = (const float*)d_in[9];
    const float* ffn_b1 = (const float*)d_in[10];
    const float* ffn_w2 = (const float*)d_in[11];
    const float* ffn_b2 = (const float*)d_in[12];
    float* out = (float*)d_out;

    __half *p_h, *p_qkv, *p_attn, *p_h2, *p_hid;
    __half *p_qkvw, *p_projw, *p_w1, *p_w2;
    float *p_xo;
    cudaGetSymbolAddress((void**)&p_h,    g_h);
    cudaGetSymbolAddress((void**)&p_qkv,  g_qkv);
    cudaGetSymbolAddress((void**)&p_attn, g_attn);
    cudaGetSymbolAddress((void**)&p_xo,   g_xo);
    cudaGetSymbolAddress((void**)&p_h2,   g_h2);
    cudaGetSymbolAddress((void**)&p_hid,  g_hid);
    cudaGetSymbolAddress((void**)&p_qkvw, g_qkvw);
    cudaGetSymbolAddress((void**)&p_projw,g_projw);
    cudaGetSymbolAddress((void**)&p_w1,   g_w1);
    cudaGetSymbolAddress((void**)&p_w2,   g_w2);

    cudaFuncSetAttribute(attn_kernel,
                         cudaFuncAttributeMaxDynamicSharedMemorySize, ATTN_SMEM);
    cudaFuncSetAttribute((tc_gemm<0, __half>), cudaFuncAttributeMaxDynamicSharedMemorySize, GEMM_SMEM);
    cudaFuncSetAttribute((tc_gemm<1, __half>), cudaFuncAttributeMaxDynamicSharedMemorySize, GEMM_SMEM);
    cudaFuncSetAttribute((tc_gemm<2, float>),  cudaFuncAttributeMaxDynamicSharedMemorySize, GEMM_SMEM);
    cudaFuncSetAttribute((tc_gemm<3, float>),  cudaFuncAttributeMaxDynamicSharedMemorySize, GEMM_SMEM);

    // 0. all weight transposes in one launch
    transpose_all<<<3072, dim3(32, 8)>>>(qkv_w, proj_w, ffn_w1, ffn_w2,
                                         p_qkvw, p_projw, p_w1, p_w2);

    // 1. shift + window partition + LN1
    ln_kernel<true><<<NROWS / 8, 256>>>(x, ln1_g, ln1_b, p_h);

    // 2. QKV GEMM
    tc_gemm<0, __half><<<dim3(QKVDIM / BN, NROWS / BM), 256, GEMM_SMEM>>>(
        p_h, p_qkvw, qkv_b, nullptr, p_qkv, NROWS, QKVDIM, CDIM);

    // 3. windowed attention (tensor cores)
    attn_kernel<<<1024 * 2, 256, ATTN_SMEM>>>(p_qkv, p_attn);

    // 4. proj GEMM + residual + window-reverse scatter
    tc_gemm<2, float><<<dim3(CDIM / BN, NROWS / BM), 256, GEMM_SMEM>>>(
        p_attn, p_projw, proj_b, x, p_xo, NROWS, CDIM, CDIM);

    // 5. LN2
    ln_kernel<false><<<NROWS / 8, 256>>>(p_xo, ln2_g, ln2_b, p_h2);

    // 6. FFN1 GEMM + GELU
    tc_gemm<1, __half><<<dim3(HIDDIM / BN, NROWS / BM), 256, GEMM_SMEM>>>(
        p_h2, p_w1, ffn_b1, nullptr, p_hid, NROWS, HIDDIM, CDIM);

    // 7. FFN2 GEMM + residual -> out
    tc_gemm<3, float><<<dim3(CDIM / BN, NROWS / BM), 256, GEMM_SMEM>>>(
        p_hid, p_w2, ffn_b2, p_xo, out, NROWS, CDIM, HIDDIM);
}

// round 16
// speedup vs baseline: 5.7671x; 1.0001x over previous
#include <cuda_runtime.h>
#include <cuda_fp16.h>
#include <math.h>
#include <stdint.h>

// ---------------------------------------------------------------------------
// Windowed 3D attention block — fp16 mma.sync GEMMs, BN=128 @ 2 CTAs/SM,
// BK=64 3-stage cp.async pipeline, register double-buffered ldmatrix
// fragments (LDSM latency hidden under HMMA); tensor-core attention.
// ---------------------------------------------------------------------------

#define NROWS   65536
#define CDIM    512
#define QKVDIM  1536
#define HIDDIM  2048

__device__ __half g_h   [ (size_t)NROWS * CDIM  ];
__device__ __half g_qkv [ (size_t)NROWS * QKVDIM];
__device__ __half g_attn[ (size_t)NROWS * CDIM  ];
__device__ float  g_xo  [ (size_t)NROWS * CDIM  ];
__device__ __half g_h2  [ (size_t)NROWS * CDIM  ];
__device__ __half g_hid [ (size_t)NROWS * HIDDIM];
__device__ __half g_qkvw [(size_t)QKVDIM * CDIM];
__device__ __half g_projw[(size_t)CDIM * CDIM  ];
__device__ __half g_w1   [(size_t)HIDDIM * CDIM];
__device__ __half g_w2   [(size_t)CDIM * HIDDIM];

// ---------------------------------------------------------------------------
__device__ __forceinline__ uint32_t smem_u32(const void* p) {
    uint32_t a;
    asm("{ .reg .u64 t; cvta.to.shared.u64 t, %1; cvt.u32.u64 %0, t; }"
        : "=r"(a) : "l"(p));
    return a;
}

__device__ __forceinline__ void cp16(void* dst, const void* src) {
    asm volatile("cp.async.cg.shared.global [%0], [%1], 16;"
                 :: "r"(smem_u32(dst)), "l"(src));
}
#define CP_COMMIT() asm volatile("cp.async.commit_group;" ::: "memory")
template <int N>
__device__ __forceinline__ void cp_wait() {
    asm volatile("cp.async.wait_group %0;" :: "n"(N) : "memory");
}

#define LDSM4(r0, r1, r2, r3, addr)                                            \
    asm volatile("ldmatrix.sync.aligned.m8n8.x4.shared.b16 {%0,%1,%2,%3}, [%4];" \
        : "=r"(r0), "=r"(r1), "=r"(r2), "=r"(r3) : "r"(addr))

#define LDSM4T(r0, r1, r2, r3, addr)                                           \
    asm volatile("ldmatrix.sync.aligned.m8n8.x4.trans.shared.b16 {%0,%1,%2,%3}, [%4];" \
        : "=r"(r0), "=r"(r1), "=r"(r2), "=r"(r3) : "r"(addr))

#define MMA_F16(d, a, b)                                                       \
    asm volatile(                                                              \
        "mma.sync.aligned.m16n8k16.row.col.f32.f16.f16.f32 "                   \
        "{%0,%1,%2,%3}, {%4,%5,%6,%7}, {%8,%9}, {%0,%1,%2,%3};"                \
        : "+f"((d)[0]), "+f"((d)[1]), "+f"((d)[2]), "+f"((d)[3])               \
        : "r"((a)[0]), "r"((a)[1]), "r"((a)[2]), "r"((a)[3]),                  \
          "r"((b)[0]), "r"((b)[1]))

// ---------------------------------------------------------------------------
__device__ __forceinline__ int mapFlat(int r) {
    int win = r >> 6, t = r & 63;
    int b  = win >> 9;
    int wd = (win >> 6) & 7, wh = (win >> 3) & 7, ww = win & 7;
    int td = t >> 4, th = (t >> 2) & 3, tw = t & 3;
    int d0 = (wd * 4 + td + 2) & 31;
    int h0 = (wh * 4 + th + 2) & 31;
    int w0 = (ww * 4 + tw + 2) & 31;
    return ((b * 32 + d0) * 32 + h0) * 32 + w0;
}

// ---------------------------------------------------------------------------
__global__ void transpose_all(
    const float* __restrict__ qkvw, const float* __restrict__ projw,
    const float* __restrict__ w1,   const float* __restrict__ w2,
    __half* __restrict__ o_qkvw, __half* __restrict__ o_projw,
    __half* __restrict__ o_w1,   __half* __restrict__ o_w2)
{
    __shared__ float t[32][33];
    int id = blockIdx.x;
    const float* in; __half* out; int K, N, nblk;
    if (id < 768)       { in = qkvw;  out = o_qkvw;  K = 512;  N = 1536; nblk = 48; }
    else if (id < 1024) { in = projw; out = o_projw; K = 512;  N = 512;  nblk = 16; id -= 768; }
    else if (id < 2048) { in = w1;    out = o_w1;    K = 512;  N = 2048; nblk = 64; id -= 1024; }
    else                { in = w2;    out = o_w2;    K = 2048; N = 512;  nblk = 16; id -= 2048; }
    int n0 = (id % nblk) * 32, k0 = (id / nblk) * 32;
    int x = threadIdx.x, y = threadIdx.y;
#pragma unroll
    for (int i = 0; i < 4; i++)
        t[y + i * 8][x] = in[(size_t)(k0 + y + i * 8) * N + n0 + x];
    __syncthreads();
#pragma unroll
    for (int i = 0; i < 4; i++)
        out[(size_t)(n0 + y + i * 8) * K + k0 + x] = __float2half_rn(t[x][y + i * 8]);
}

// ---------------------------------------------------------------------------
template <bool MAPPED>
__global__ void __launch_bounds__(256) ln_kernel(
    const float* __restrict__ in, const float* __restrict__ gam,
    const float* __restrict__ bet, __half* __restrict__ out)
{
    int warp = threadIdx.x >> 5, lane = threadIdx.x & 31;
    int r = blockIdx.x * 8 + warp;
    int src = MAPPED ? mapFlat(r) : r;

    const float4* ip = (const float4*)(in + (size_t)src * CDIM);
    float4 vals[4];
    float s = 0.f, sq = 0.f;
#pragma unroll
    for (int w = 0; w < 4; w++) {
        float4 v = ip[w * 32 + lane];
        vals[w] = v;
        s  += v.x + v.y + v.z + v.w;
        sq += v.x * v.x + v.y * v.y + v.z * v.z + v.w * v.w;
    }
#pragma unroll
    for (int o = 16; o > 0; o >>= 1) {
        s  += __shfl_xor_sync(0xffffffffu, s,  o);
        sq += __shfl_xor_sync(0xffffffffu, sq, o);
    }
    float m  = s * (1.0f / CDIM);
    float var = sq * (1.0f / CDIM) - m * m;
    float rs = rsqrtf(var + 1e-5f);

    __half2* op = (__half2*)(out + (size_t)r * CDIM);
    const float4* gp = (const float4*)gam;
    const float4* bp = (const float4*)bet;
#pragma unroll
    for (int w = 0; w < 4; w++) {
        int c4 = w * 32 + lane;
        float4 g = gp[c4], b = bp[c4], x = vals[w];
        op[c4 * 2]     = __floats2half2_rn((x.x - m) * rs * g.x + b.x,
                                           (x.y - m) * rs * g.y + b.y);
        op[c4 * 2 + 1] = __floats2half2_rn((x.z - m) * rs * g.z + b.z,
                                           (x.w - m) * rs * g.w + b.w);
    }
}

// ---------------------------------------------------------------------------
// fp16 GEMM: C[M,N] = A[M,K] @ Bt[N,K]^T  (block 128x128, BK=64, 3 stages,
// 2 CTAs/SM, register double-buffered fragments).
// ---------------------------------------------------------------------------
#define BM 128
#define BN 128
#define BK 64
#define ASTR 72
#define A_HALFS (BM * ASTR)
#define B_HALFS (BN * ASTR)
#define STAGES 3
#define GEMM_SMEM (STAGES * (A_HALFS + B_HALFS) * 2)   // 110592 B

template <int EPI, typename OutT>
__global__ void __launch_bounds__(256, 2) tc_gemm(
    const __half* __restrict__ A, const __half* __restrict__ Bt,
    const float* __restrict__ bias, const float* __restrict__ resid,
    OutT* __restrict__ C, int M, int N, int K)
{
    extern __shared__ __half smh[];
    __half* Asm[STAGES];
    __half* Bsm[STAGES];
    uint32_t Au[STAGES], Bu[STAGES];
#pragma unroll
    for (int s = 0; s < STAGES; s++) {
        Asm[s] = smh + s * A_HALFS;
        Bsm[s] = smh + STAGES * A_HALFS + s * B_HALFS;
        Au[s] = smem_u32(Asm[s]);
        Bu[s] = smem_u32(Bsm[s]);
    }

    int tid = threadIdx.x;
    int wid = tid >> 5, lane = tid & 31;
    int wm = wid >> 1, wn = wid & 1;          // 4 x 2 warp grid
    int lr = lane >> 2, lc = lane & 3;
    int m0 = blockIdx.y * BM, n0 = blockIdx.x * BN;

    int a_lane = ((lane & 7) + ((lane >> 3) & 1) * 8) * ASTR + (lane >> 4) * 8
               + wm * 32 * ASTR;
    int b_lane = ((lane & 7) + (lane >> 4) * 8) * ASTR + ((lane >> 3) & 1) * 8
               + wn * 64 * ASTR;

    float acc[2][8][4];
#pragma unroll
    for (int i = 0; i < 2; i++)
#pragma unroll
        for (int j = 0; j < 8; j++)
#pragma unroll
            for (int q = 0; q < 4; q++) acc[i][j][q] = 0.f;

    const int NCH = K >> 6;

    auto issue = [&](int it) {
        int s = it % STAGES;
        const __half* Ab = A + (size_t)m0 * K + it * BK;
#pragma unroll
        for (int i = 0; i < 4; i++) {
            int idx = i * 256 + tid;
            int row = idx >> 3, c = idx & 7;
            cp16(Asm[s] + row * ASTR + c * 8, Ab + (size_t)row * K + c * 8);
        }
        const __half* Bb = Bt + (size_t)n0 * K + it * BK;
#pragma unroll
        for (int i = 0; i < 4; i++) {
            int idx = i * 256 + tid;
            int row = idx >> 3, c = idx & 7;
            cp16(Bsm[s] + row * ASTR + c * 8, Bb + (size_t)row * K + c * 8);
        }
        CP_COMMIT();
    };

    issue(0);
    issue(1);

    // Double-buffered fragments: load ks+1 while HMMAs consume ks.
    uint32_t a[2][2][4], b[2][8][2];

    for (int it = 0; it < NCH; it++) {
        if (it + 1 < NCH) cp_wait<1>();
        else              cp_wait<0>();
        __syncthreads();
        if (it + 2 < NCH) issue(it + 2);

        int s = it % STAGES;

        auto ldA = [&](int buf, int ks) {
#pragma unroll
            for (int mi = 0; mi < 2; mi++)
                LDSM4(a[buf][mi][0], a[buf][mi][1], a[buf][mi][2], a[buf][mi][3],
                      Au[s] + 2 * (a_lane + mi * 16 * ASTR + ks * 16));
        };
        auto ldB = [&](int buf, int ks) {
#pragma unroll
            for (int np = 0; np < 4; np++)
                LDSM4(b[buf][2 * np][0], b[buf][2 * np][1],
                      b[buf][2 * np + 1][0], b[buf][2 * np + 1][1],
                      Bu[s] + 2 * (b_lane + np * 16 * ASTR + ks * 16));
        };

        ldA(0, 0); ldB(0, 0);
#pragma unroll
        for (int ks = 0; ks < 4; ks++) {
            int cur = ks & 1, nxt = cur ^ 1;
            if (ks < 3) { ldA(nxt, ks + 1); ldB(nxt, ks + 1); }
#pragma unroll
            for (int mi = 0; mi < 2; mi++)
#pragma unroll
                for (int ni = 0; ni < 8; ni++)
                    MMA_F16(acc[mi][ni], a[cur][mi], b[cur][ni]);
        }
    }

    // Epilogue
#pragma unroll
    for (int mi = 0; mi < 2; mi++) {
        int r0 = m0 + wm * 32 + mi * 16 + lr;
        size_t rb0, rb1;
        if (EPI == 2) { rb0 = (size_t)mapFlat(r0) * CDIM;
                        rb1 = (size_t)mapFlat(r0 + 8) * CDIM; }
        else          { rb0 = (size_t)r0 * N; rb1 = rb0 + (size_t)8 * N; }
#pragma unroll
        for (int ni = 0; ni < 8; ni++) {
            int c = n0 + wn * 64 + ni * 8 + lc * 2;
            float2 bs = *(const float2*)(bias + c);
            float v0 = acc[mi][ni][0] + bs.x, v1 = acc[mi][ni][1] + bs.y;
            float v2 = acc[mi][ni][2] + bs.x, v3 = acc[mi][ni][3] + bs.y;
            if (EPI == 1) {
                v0 = 0.5f * v0 * (1.0f + erff(v0 * 0.70710678118654752f));
                v1 = 0.5f * v1 * (1.0f + erff(v1 * 0.70710678118654752f));
                v2 = 0.5f * v2 * (1.0f + erff(v2 * 0.70710678118654752f));
                v3 = 0.5f * v3 * (1.0f + erff(v3 * 0.70710678118654752f));
            }
            if (EPI == 2 || EPI == 3) {
                float2 r0v = *(const float2*)(resid + rb0 + c);
                float2 r1v = *(const float2*)(resid + rb1 + c);
                v0 += r0v.x; v1 += r0v.y; v2 += r1v.x; v3 += r1v.y;
                float* Cf = (float*)C;
                *(float2*)(Cf + rb0 + c) = make_float2(v0, v1);
                *(float2*)(Cf + rb1 + c) = make_float2(v2, v3);
            } else {
                __half* Ch = (__half*)C;
                *(__half2*)(Ch + rb0 + c) = __floats2half2_rn(v0, v1);
                *(__half2*)(Ch + rb1 + c) = __floats2half2_rn(v2, v3);
            }
        }
    }
}

// ---------------------------------------------------------------------------
// Tensor-core windowed attention. Block = (window, 4 heads), 8 warps.
// ---------------------------------------------------------------------------
#define HP 72
#define ATTN_SMEM (4 * 3 * 64 * HP * 2)

__global__ void __launch_bounds__(256) attn_kernel(
    const __half* __restrict__ qkv, __half* __restrict__ out)
{
    extern __shared__ __half sh[];
    int tid = threadIdx.x, wid = tid >> 5, lane = tid & 31;
    int lr = lane >> 2, lc = lane & 3;
    int win = blockIdx.x >> 1;
    int head = (blockIdx.x & 1) * 4 + (wid >> 1);
    int mh = wid & 1;

    __half* Qs = sh + (wid >> 1) * 3 * 64 * HP;
    __half* Ks = Qs + 64 * HP;
    __half* Vs = Ks + 64 * HP;
    const __half* base = qkv + (size_t)win * 64 * QKVDIM + head * 64;

#pragma unroll
    for (int i = 0; i < 24; i++) {
        int idx = i * 32 + lane;
        int tens = idx >> 8;
        int rem = idx & 255;
        int t = mh * 32 + (rem >> 3), c = rem & 7;
        const uint4* gp = (const uint4*)(base + (size_t)t * QKVDIM + tens * 512 + c * 8);
        __half* dst = (tens == 0 ? Qs : tens == 1 ? Ks : Vs) + t * HP + c * 8;
        *(uint4*)dst = *gp;
    }
    __syncthreads();

    uint32_t qb = smem_u32(Qs), kb = smem_u32(Ks), vb = smem_u32(Vs);
    int a_lane = ((lane & 7) + ((lane >> 3) & 1) * 8) * HP + (lane >> 4) * 8;
    int b_lane = ((lane & 7) + (lane >> 4) * 8) * HP + ((lane >> 3) & 1) * 8;

    float sacc[2][8][4];
#pragma unroll
    for (int i = 0; i < 2; i++)
#pragma unroll
        for (int j = 0; j < 8; j++)
#pragma unroll
            for (int q = 0; q < 4; q++) sacc[i][j][q] = 0.f;

#pragma unroll
    for (int ks = 0; ks < 4; ks++) {
        uint32_t a[2][4];
#pragma unroll
        for (int mi = 0; mi < 2; mi++)
            LDSM4(a[mi][0], a[mi][1], a[mi][2], a[mi][3],
                  qb + 2 * (mh * 32 * HP + mi * 16 * HP + ks * 16 + a_lane));
        uint32_t b[8][2];
#pragma unroll
        for (int np = 0; np < 4; np++)
            LDSM4(b[2 * np][0], b[2 * np][1], b[2 * np + 1][0], b[2 * np + 1][1],
                  kb + 2 * (np * 16 * HP + ks * 16 + b_lane));
#pragma unroll
        for (int mi = 0; mi < 2; mi++)
#pragma unroll
            for (int ni = 0; ni < 8; ni++)
                MMA_F16(sacc[mi][ni], a[mi], b[ni]);
    }

#pragma unroll
    for (int mi = 0; mi < 2; mi++) {
        float mx0 = -1e30f, mx1 = -1e30f;
#pragma unroll
        for (int ni = 0; ni < 8; ni++) {
#pragma unroll
            for (int q = 0; q < 4; q++) sacc[mi][ni][q] *= 0.125f;
            mx0 = fmaxf(mx0, fmaxf(sacc[mi][ni][0], sacc[mi][ni][1]));
            mx1 = fmaxf(mx1, fmaxf(sacc[mi][ni][2], sacc[mi][ni][3]));
        }
        mx0 = fmaxf(mx0, __shfl_xor_sync(0xffffffffu, mx0, 1));
        mx0 = fmaxf(mx0, __shfl_xor_sync(0xffffffffu, mx0, 2));
        mx1 = fmaxf(mx1, __shfl_xor_sync(0xffffffffu, mx1, 1));
        mx1 = fmaxf(mx1, __shfl_xor_sync(0xffffffffu, mx1, 2));
        float s0 = 0.f, s1 = 0.f;
#pragma unroll
        for (int ni = 0; ni < 8; ni++) {
            sacc[mi][ni][0] = __expf(sacc[mi][ni][0] - mx0);
            sacc[mi][ni][1] = __expf(sacc[mi][ni][1] - mx0);
            sacc[mi][ni][2] = __expf(sacc[mi][ni][2] - mx1);
            sacc[mi][ni][3] = __expf(sacc[mi][ni][3] - mx1);
            s0 += sacc[mi][ni][0] + sacc[mi][ni][1];
            s1 += sacc[mi][ni][2] + sacc[mi][ni][3];
        }
        s0 += __shfl_xor_sync(0xffffffffu, s0, 1);
        s0 += __shfl_xor_sync(0xffffffffu, s0, 2);
        s1 += __shfl_xor_sync(0xffffffffu, s1, 1);
        s1 += __shfl_xor_sync(0xffffffffu, s1, 2);
        float i0 = 1.0f / s0, i1 = 1.0f / s1;
        int row0 = mh * 32 + mi * 16 + lr;
#pragma unroll
        for (int ni = 0; ni < 8; ni++) {
            int cc = ni * 8 + lc * 2;
            *(__half2*)(Qs + row0 * HP + cc) =
                __floats2half2_rn(sacc[mi][ni][0] * i0, sacc[mi][ni][1] * i0);
            *(__half2*)(Qs + (row0 + 8) * HP + cc) =
                __floats2half2_rn(sacc[mi][ni][2] * i1, sacc[mi][ni][3] * i1);
        }
    }
    __syncwarp();

    float oacc[2][8][4];
#pragma unroll
    for (int i = 0; i < 2; i++)
#pragma unroll
        for (int j = 0; j < 8; j++)
#pragma unroll
            for (int q = 0; q < 4; q++) oacc[i][j][q] = 0.f;

#pragma unroll
    for (int ks = 0; ks < 4; ks++) {
        uint32_t a[2][4];
#pragma unroll
        for (int mi = 0; mi < 2; mi++)
            LDSM4(a[mi][0], a[mi][1], a[mi][2], a[mi][3],
                  qb + 2 * (mh * 32 * HP + mi * 16 * HP + ks * 16 + a_lane));
        uint32_t b[8][2];
#pragma unroll
        for (int np = 0; np < 4; np++)
            LDSM4T(b[2 * np][0], b[2 * np][1], b[2 * np + 1][0], b[2 * np + 1][1],
                   vb + 2 * (ks * 16 * HP + np * 16 + a_lane));
#pragma unroll
        for (int mi = 0; mi < 2; mi++)
#pragma unroll
            for (int ni = 0; ni < 8; ni++)
                MMA_F16(oacc[mi][ni], a[mi], b[ni]);
    }

#pragma unroll
    for (int mi = 0; mi < 2; mi++) {
        int row0 = win * 64 + mh * 32 + mi * 16 + lr;
#pragma unroll
        for (int ni = 0; ni < 8; ni++) {
            int col = head * 64 + ni * 8 + lc * 2;
            *(__half2*)(out + (size_t)row0 * CDIM + col) =
                __floats2half2_rn(oacc[mi][ni][0], oacc[mi][ni][1]);
            *(__half2*)(out + (size_t)(row0 + 8) * CDIM + col) =
                __floats2half2_rn(oacc[mi][ni][2], oacc[mi][ni][3]);
        }
    }
}

// ---------------------------------------------------------------------------
extern "C" void kernel_launch(void* const* d_in, const int* in_sizes, int n_in,
                              void* d_out, int out_size)
{
    const float* x      = (const float*)d_in[0];
    const float* ln1_g  = (const float*)d_in[1];
    const float* ln1_b  = (const float*)d_in[2];
    const float* qkv_w  = (const float*)d_in[3];
    const float* qkv_b  = (const float*)d_in[4];
    const float* proj_w = (const float*)d_in[5];
    const float* proj_b = (const float*)d_in[6];
    const float* ln2_g  = (const float*)d_in[7];
    const float* ln2_b  = (const float*)d_in[8];
    const float* ffn_w1 = (const float*)d_in[9];
    const float* ffn_b1 = (const float*)d_in[10];
    const float* ffn_w2 = (const float*)d_in[11];
    const float* ffn_b2 = (const float*)d_in[12];
    float* out = (float*)d_out;

    __half *p_h, *p_qkv, *p_attn, *p_h2, *p_hid;
    __half *p_qkvw, *p_projw, *p_w1, *p_w2;
    float *p_xo;
    cudaGetSymbolAddress((void**)&p_h,    g_h);
    cudaGetSymbolAddress((void**)&p_qkv,  g_qkv);
    cudaGetSymbolAddress((void**)&p_attn, g_attn);
    cudaGetSymbolAddress((void**)&p_xo,   g_xo);
    cudaGetSymbolAddress((void**)&p_h2,   g_h2);
    cudaGetSymbolAddress((void**)&p_hid,  g_hid);
    cudaGetSymbolAddress((void**)&p_qkvw, g_qkvw);
    cudaGetSymbolAddress((void**)&p_projw,g_projw);
    cudaGetSymbolAddress((void**)&p_w1,   g_w1);
    cudaGetSymbolAddress((void**)&p_w2,   g_w2);

    cudaFuncSetAttribute(attn_kernel,
                         cudaFuncAttributeMaxDynamicSharedMemorySize, ATTN_SMEM);
    cudaFuncSetAttribute((tc_gemm<0, __half>), cudaFuncAttributeMaxDynamicSharedMemorySize, GEMM_SMEM);
    cudaFuncSetAttribute((tc_gemm<1, __half>), cudaFuncAttributeMaxDynamicSharedMemorySize, GEMM_SMEM);
    cudaFuncSetAttribute((tc_gemm<2, float>),  cudaFuncAttributeMaxDynamicSharedMemorySize, GEMM_SMEM);
    cudaFuncSetAttribute((tc_gemm<3, float>),  cudaFuncAttributeMaxDynamicSharedMemorySize, GEMM_SMEM);

    // 0. all weight transposes in one launch
    transpose_all<<<3072, dim3(32, 8)>>>(qkv_w, proj_w, ffn_w1, ffn_w2,
                                         p_qkvw, p_projw, p_w1, p_w2);

    // 1. shift + window partition + LN1
    ln_kernel<true><<<NROWS / 8, 256>>>(x, ln1_g, ln1_b, p_h);

    // 2. QKV GEMM
    tc_gemm<0, __half><<<dim3(QKVDIM / BN, NROWS / BM), 256, GEMM_SMEM>>>(
        p_h, p_qkvw, qkv_b, nullptr, p_qkv, NROWS, QKVDIM, CDIM);

    // 3. windowed attention (tensor cores)
    attn_kernel<<<1024 * 2, 256, ATTN_SMEM>>>(p_qkv, p_attn);

    // 4. proj GEMM + residual + window-reverse scatter
    tc_gemm<2, float><<<dim3(CDIM / BN, NROWS / BM), 256, GEMM_SMEM>>>(
        p_attn, p_projw, proj_b, x, p_xo, NROWS, CDIM, CDIM);

    // 5. LN2
    ln_kernel<false><<<NROWS / 8, 256>>>(p_xo, ln2_g, ln2_b, p_h2);

    // 6. FFN1 GEMM + GELU
    tc_gemm<1, __half><<<dim3(HIDDIM / BN, NROWS / BM), 256, GEMM_SMEM>>>(
        p_h2, p_w1, ffn_b1, nullptr, p_hid, NROWS, HIDDIM, CDIM);

    // 7. FFN2 GEMM + residual -> out
    tc_gemm<3, float><<<dim3(CDIM / BN, NROWS / BM), 256, GEMM_SMEM>>>(
        p_hid, p_w2, ffn_b2, p_xo, out, NROWS, CDIM, HIDDIM);
}